// round 2
// baseline (speedup 1.0000x reference)
#include <cuda_runtime.h>
#include <math.h>

// ---------------------------------------------------------------------------
// Problem constants
// ---------------------------------------------------------------------------
#define B_   16
#define LP_  1024
#define LD_  256
#define DP_  1280
#define DE_  512
#define LC_  256

#define MPR  (B_ * LP_)      // 16384
#define MDR  (B_ * LD_)      // 4096

// ---------------------------------------------------------------------------
// Scratch (device globals; no allocation allowed)
// ---------------------------------------------------------------------------
__device__ float g_Qpr[(size_t)MPR * DP_];     // 16384 x 1280
__device__ float g_Kpr[(size_t)LC_ * DP_];     // 256 x 1280
__device__ float g_att_pr[(size_t)MPR * LC_];  // 16384 x 256
__device__ float g_Qa_pr[(size_t)MPR * DP_];   // 16384 x 1280
__device__ float g_Qdr[(size_t)MDR * DE_];     // 4096 x 512
__device__ float g_Kdr[(size_t)LC_ * DE_];     // 256 x 512
__device__ float g_att_dr[(size_t)MDR * LC_];  // 4096 x 256

// ---------------------------------------------------------------------------
// Tiled fp32 GEMM (NN):  C[m,n] = alpha * sum_k A[m,k]*B[k,n] (+bias) (+C)
// BM=BN=64, BK=16, 256 threads, 4x4 per thread. All dims multiples of tiles.
// ---------------------------------------------------------------------------
#define BM 64
#define BN 64
#define BKK 16

__global__ __launch_bounds__(256) void gemm_nn_kernel(
    const float* __restrict__ A, int lda,
    const float* __restrict__ B, int ldb,
    float* __restrict__ C, int ldc,
    const float* __restrict__ bias,
    int K, float alpha, int accum)
{
    __shared__ float As[BKK][BM + 4];
    __shared__ float Bs[BKK][BN + 4];

    const int tid = threadIdx.x;
    const int tx = tid & 15;        // n direction (16)
    const int ty = tid >> 4;        // m direction (16)
    const int m0 = blockIdx.y * BM;
    const int n0 = blockIdx.x * BN;

    // A-tile load mapping: k = tid%16, m = tid/16 (+16*r)
    const int a_k = tid & 15;
    const int a_m = tid >> 4;
    // B-tile load mapping: n = tid%64, k = tid/64 (+4*r)
    const int b_n = tid & 63;
    const int b_k = tid >> 6;

    const float* Aptr = A + (size_t)m0 * lda;
    const float* Bptr = B + n0;

    float acc[4][4] = {};

    for (int k0 = 0; k0 < K; k0 += BKK) {
        #pragma unroll
        for (int r = 0; r < 4; r++)
            As[a_k][a_m + 16 * r] = Aptr[(size_t)(a_m + 16 * r) * lda + k0 + a_k];
        #pragma unroll
        for (int r = 0; r < 4; r++)
            Bs[b_k + 4 * r][b_n] = Bptr[(size_t)(k0 + b_k + 4 * r) * ldb + b_n];
        __syncthreads();

        #pragma unroll
        for (int k = 0; k < BKK; k++) {
            float4 ra = *(const float4*)&As[k][ty * 4];
            float4 rb = *(const float4*)&Bs[k][tx * 4];
            float av[4] = {ra.x, ra.y, ra.z, ra.w};
            float bv[4] = {rb.x, rb.y, rb.z, rb.w};
            #pragma unroll
            for (int i = 0; i < 4; i++)
                #pragma unroll
                for (int j = 0; j < 4; j++)
                    acc[i][j] = fmaf(av[i], bv[j], acc[i][j]);
        }
        __syncthreads();
    }

    #pragma unroll
    for (int i = 0; i < 4; i++) {
        const int m = m0 + ty * 4 + i;
        #pragma unroll
        for (int j = 0; j < 4; j++) {
            const int n = n0 + tx * 4 + j;
            float v = alpha * acc[i][j];
            if (bias) v += bias[n];
            size_t cidx = (size_t)m * ldc + n;
            if (accum) v += C[cidx];
            C[cidx] = v;
        }
    }
}

// ---------------------------------------------------------------------------
// Tiled fp32 GEMM (NT): C[m,n] = alpha * sum_k A[m,k]*B[n,k]
// ---------------------------------------------------------------------------
__global__ __launch_bounds__(256) void gemm_nt_kernel(
    const float* __restrict__ A, int lda,
    const float* __restrict__ B, int ldb,   // B is [N, K] row-major
    float* __restrict__ C, int ldc,
    int K, float alpha)
{
    __shared__ float As[BKK][BM + 4];
    __shared__ float Bs[BKK][BN + 4];

    const int tid = threadIdx.x;
    const int tx = tid & 15;
    const int ty = tid >> 4;
    const int m0 = blockIdx.y * BM;
    const int n0 = blockIdx.x * BN;

    const int t_k = tid & 15;   // k
    const int t_r = tid >> 4;   // row within tile (+16*r)

    const float* Aptr = A + (size_t)m0 * lda;
    const float* Bptr = B + (size_t)n0 * ldb;

    float acc[4][4] = {};

    for (int k0 = 0; k0 < K; k0 += BKK) {
        #pragma unroll
        for (int r = 0; r < 4; r++)
            As[t_k][t_r + 16 * r] = Aptr[(size_t)(t_r + 16 * r) * lda + k0 + t_k];
        #pragma unroll
        for (int r = 0; r < 4; r++)
            Bs[t_k][t_r + 16 * r] = Bptr[(size_t)(t_r + 16 * r) * ldb + k0 + t_k];
        __syncthreads();

        #pragma unroll
        for (int k = 0; k < BKK; k++) {
            float4 ra = *(const float4*)&As[k][ty * 4];
            float4 rb = *(const float4*)&Bs[k][tx * 4];
            float av[4] = {ra.x, ra.y, ra.z, ra.w};
            float bv[4] = {rb.x, rb.y, rb.z, rb.w};
            #pragma unroll
            for (int i = 0; i < 4; i++)
                #pragma unroll
                for (int j = 0; j < 4; j++)
                    acc[i][j] = fmaf(av[i], bv[j], acc[i][j]);
        }
        __syncthreads();
    }

    #pragma unroll
    for (int i = 0; i < 4; i++) {
        const int m = m0 + ty * 4 + i;
        #pragma unroll
        for (int j = 0; j < 4; j++) {
            const int n = n0 + tx * 4 + j;
            C[(size_t)m * ldc + n] = alpha * acc[i][j];
        }
    }
}

// ---------------------------------------------------------------------------
// Masked softmax over LC=256 columns. One block (256 threads) per row.
// mask is int32 (bool serialized as int32). mask[row] != 0 => uniform 1/256.
// ---------------------------------------------------------------------------
__global__ __launch_bounds__(256) void softmax_mask_kernel(
    float* __restrict__ att, const int* __restrict__ mask)
{
    const int row = blockIdx.x;
    const int c = threadIdx.x;     // 0..255
    const size_t idx = (size_t)row * LC_ + c;

    float v = att[idx];
    if (mask[row] != 0) v = -1e10f;

    __shared__ float red_max[8];
    __shared__ float red_sum[8];
    const int lane = c & 31;
    const int warp = c >> 5;

    float m = v;
    #pragma unroll
    for (int o = 16; o > 0; o >>= 1)
        m = fmaxf(m, __shfl_xor_sync(0xffffffffu, m, o));
    if (lane == 0) red_max[warp] = m;
    __syncthreads();
    float mmax = red_max[0];
    #pragma unroll
    for (int i = 1; i < 8; i++) mmax = fmaxf(mmax, red_max[i]);

    float e = expf(v - mmax);

    float s = e;
    #pragma unroll
    for (int o = 16; o > 0; o >>= 1)
        s += __shfl_xor_sync(0xffffffffu, s, o);
    if (lane == 0) red_sum[warp] = s;
    __syncthreads();
    float ssum = red_sum[0];
    #pragma unroll
    for (int i = 1; i < 8; i++) ssum += red_sum[i];

    att[idx] = e / ssum;
}

// ---------------------------------------------------------------------------
// Copy drug_f into first half of drug output rows (row stride 2*DE)
// ---------------------------------------------------------------------------
__global__ __launch_bounds__(256) void copy_drug_kernel(
    const float* __restrict__ drug_f, float* __restrict__ out)
{
    const int idx = blockIdx.x * blockDim.x + threadIdx.x;   // 0 .. 4096*128-1
    if (idx >= MDR * (DE_ / 4)) return;
    const int m = idx / (DE_ / 4);
    const int n4 = idx % (DE_ / 4);
    const float4 v = ((const float4*)drug_f)[(size_t)m * (DE_ / 4) + n4];
    ((float4*)out)[(size_t)m * (2 * DE_ / 4) + n4] = v;
}

// ---------------------------------------------------------------------------
// Launch
// ---------------------------------------------------------------------------
extern "C" void kernel_launch(void* const* d_in, const int* in_sizes, int n_in,
                              void* d_out, int out_size)
{
    const float* pr_f    = (const float*)d_in[0];
    const float* drug_f  = (const float*)d_in[1];
    const float* pr_conf = (const float*)d_in[2];
    const float* dr_conf = (const float*)d_in[3];
    const float* Wq  = (const float*)d_in[4];
    const float* bq  = (const float*)d_in[5];
    const float* Wk  = (const float*)d_in[6];
    const float* bk  = (const float*)d_in[7];
    const float* Wq2 = (const float*)d_in[8];
    const float* bq2 = (const float*)d_in[9];
    const float* Wk2 = (const float*)d_in[10];
    const float* bk2 = (const float*)d_in[11];
    const float* Wpr = (const float*)d_in[12];
    const float* bpr = (const float*)d_in[13];
    const int* pmask = (const int*)d_in[14];
    const int* dmask = (const int*)d_in[15];

    float* out    = (float*)d_out;
    float* pr_out = out;                                  // [16384, 512]
    float* dr_out = out + (size_t)MPR * DE_;              // [4096, 1024]

    float *Qpr, *Kpr, *att_pr, *Qa_pr, *Qdr, *Kdr, *att_dr;
    cudaGetSymbolAddress((void**)&Qpr,    g_Qpr);
    cudaGetSymbolAddress((void**)&Kpr,    g_Kpr);
    cudaGetSymbolAddress((void**)&att_pr, g_att_pr);
    cudaGetSymbolAddress((void**)&Qa_pr,  g_Qa_pr);
    cudaGetSymbolAddress((void**)&Qdr,    g_Qdr);
    cudaGetSymbolAddress((void**)&Kdr,    g_Kdr);
    cudaGetSymbolAddress((void**)&att_dr, g_att_dr);

    const float pr_alpha = 1.0f / 16.0f;                 // 1/sqrt(LC=256)
    const float dr_alpha = 1.0f / sqrtf((float)DE_);     // 1/sqrt(512)

    // ---------------- Protein path ----------------
    // 1) Qpr = pr_f @ Wq + bq            [16384,1280]
    gemm_nn_kernel<<<dim3(DP_ / BN, MPR / BM), 256>>>(
        pr_f, DP_, Wq, DP_, Qpr, DP_, bq, DP_, 1.0f, 0);
    // 2) Kpr = pr_conf @ Wk + bk         [256,1280]
    gemm_nn_kernel<<<dim3(DP_ / BN, LC_ / BM), 256>>>(
        pr_conf, DP_, Wk, DP_, Kpr, DP_, bk, DP_, 1.0f, 0);
    // 3) att_pr = (Qpr @ Kpr^T) / 16     [16384,256]
    gemm_nt_kernel<<<dim3(LC_ / BN, MPR / BM), 256>>>(
        Qpr, DP_, Kpr, DP_, att_pr, LC_, DP_, pr_alpha);
    // 4) softmax with protein mask
    softmax_mask_kernel<<<MPR, 256>>>(att_pr, pmask);
    // 5) Qa_pr = att_pr @ Kpr            [16384,1280]
    gemm_nn_kernel<<<dim3(DP_ / BN, MPR / BM), 256>>>(
        att_pr, LC_, Kpr, DP_, Qa_pr, DP_, (const float*)0, LC_, 1.0f, 0);
    // 6) pr_out = pr_f @ Wpr[0:1280] + bpr
    gemm_nn_kernel<<<dim3(DE_ / BN, MPR / BM), 256>>>(
        pr_f, DP_, Wpr, DE_, pr_out, DE_, bpr, DP_, 1.0f, 0);
    // 7) pr_out += Qa_pr @ Wpr[1280:2560]
    gemm_nn_kernel<<<dim3(DE_ / BN, MPR / BM), 256>>>(
        Qa_pr, DP_, Wpr + (size_t)DP_ * DE_, DE_, pr_out, DE_,
        (const float*)0, DP_, 1.0f, 1);

    // ---------------- Drug path ----------------
    // 8) Qdr = drug_f @ Wq2 + bq2        [4096,512]
    gemm_nn_kernel<<<dim3(DE_ / BN, MDR / BM), 256>>>(
        drug_f, DE_, Wq2, DE_, Qdr, DE_, bq2, DE_, 1.0f, 0);
    // 9) Kdr = dr_conf @ Wk2 + bk2       [256,512]
    gemm_nn_kernel<<<dim3(DE_ / BN, LC_ / BM), 256>>>(
        dr_conf, DE_, Wk2, DE_, Kdr, DE_, bk2, DE_, 1.0f, 0);
    // 10) att_dr = (Qdr @ Kdr^T) / sqrt(512)
    gemm_nt_kernel<<<dim3(LC_ / BN, MDR / BM), 256>>>(
        Qdr, DE_, Kdr, DE_, att_dr, LC_, DE_, dr_alpha);
    // 11) softmax with drug mask
    softmax_mask_kernel<<<MDR, 256>>>(att_dr, dmask);
    // 12) dr_out[:, 512:1024] = att_dr @ Kdr
    gemm_nn_kernel<<<dim3(DE_ / BN, MDR / BM), 256>>>(
        att_dr, LC_, Kdr, DE_, dr_out + DE_, 2 * DE_, (const float*)0,
        LC_, 1.0f, 0);
    // 13) dr_out[:, 0:512] = drug_f
    const int ncopy = MDR * (DE_ / 4);
    copy_drug_kernel<<<(ncopy + 255) / 256, 256>>>(drug_f, dr_out);
}

// round 4
// speedup vs baseline: 2.2955x; 2.2955x over previous
#include <cuda_runtime.h>
#include <cuda_bf16.h>
#include <cstdint>
#include <math.h>

// ---------------------------------------------------------------------------
// Problem constants
// ---------------------------------------------------------------------------
#define B_   16
#define LP_  1024
#define LD_  256
#define DP_  1280
#define DE_  512
#define LC_  256

#define MPR  (B_ * LP_)      // 16384
#define MDR  (B_ * LD_)      // 4096

// ---------------------------------------------------------------------------
// Helpers (sm_80-era path: cp.async + ldmatrix + mma.sync — valid on sm_103 base)
// ---------------------------------------------------------------------------
__device__ __forceinline__ uint32_t smem_u32(const void* p) {
    uint32_t a;
    asm("{ .reg .u64 t; cvta.to.shared.u64 t, %1; cvt.u32.u64 %0, t; }"
        : "=r"(a) : "l"(p));
    return a;
}

__device__ __forceinline__ void cpa16(uint32_t saddr, const void* g) {
    asm volatile("cp.async.cg.shared.global [%0], [%1], 16;"
                 :: "r"(saddr), "l"(g) : "memory");
}
#define CP_COMMIT() asm volatile("cp.async.commit_group;" ::: "memory")
#define CP_WAIT0()  asm volatile("cp.async.wait_group 0;" ::: "memory")
#define CP_WAIT1()  asm volatile("cp.async.wait_group 1;" ::: "memory")

#define LDSM4(r, addr) \
    asm volatile("ldmatrix.sync.aligned.m8n8.x4.shared.b16 {%0,%1,%2,%3}, [%4];" \
        : "=r"((r)[0]), "=r"((r)[1]), "=r"((r)[2]), "=r"((r)[3]) : "r"(addr))

#define MMA16816(d, a, b) \
    asm volatile("mma.sync.aligned.m16n8k16.row.col.f32.bf16.bf16.f32 " \
        "{%0,%1,%2,%3}, {%4,%5,%6,%7}, {%8,%9}, {%0,%1,%2,%3};" \
        : "+f"((d)[0]), "+f"((d)[1]), "+f"((d)[2]), "+f"((d)[3]) \
        : "r"((a)[0]), "r"((a)[1]), "r"((a)[2]), "r"((a)[3]), \
          "r"((b)[0]), "r"((b)[1]))

// ---------------------------------------------------------------------------
// Scratch (bf16 buffers: hi at [0,sz), lo at [sz,2sz)); 16B aligned
// ---------------------------------------------------------------------------
__device__ __align__(16) __nv_bfloat16 g_prf   [2ull * MPR * DP_];
__device__ __align__(16) __nv_bfloat16 g_drugf [2ull * MDR * DE_];
__device__ __align__(16) __nv_bfloat16 g_prconf[2ull * LC_ * DP_];
__device__ __align__(16) __nv_bfloat16 g_drconf[2ull * LC_ * DE_];
__device__ __align__(16) __nv_bfloat16 g_WqT   [2ull * DP_ * DP_];
__device__ __align__(16) __nv_bfloat16 g_WkT   [2ull * DP_ * DP_];
__device__ __align__(16) __nv_bfloat16 g_Wq2T  [2ull * DE_ * DE_];
__device__ __align__(16) __nv_bfloat16 g_Wk2T  [2ull * DE_ * DE_];
__device__ __align__(16) __nv_bfloat16 g_WprTt [2ull * DE_ * DP_];
__device__ __align__(16) __nv_bfloat16 g_WprTb [2ull * DE_ * DP_];
__device__ __align__(16) __nv_bfloat16 g_Qpr   [2ull * MPR * DP_];
__device__ __align__(16) float         g_Kpr   [(size_t)LC_ * DP_];
__device__ __align__(16) __nv_bfloat16 g_Kprhl [2ull * LC_ * DP_];
__device__ __align__(16) __nv_bfloat16 g_KprT  [2ull * DP_ * LC_];
__device__ __align__(16) float         g_att   [(size_t)MPR * LC_];
__device__ __align__(16) __nv_bfloat16 g_atthl [2ull * MPR * LC_];
__device__ __align__(16) __nv_bfloat16 g_Qa    [2ull * MPR * DP_];
__device__ __align__(16) __nv_bfloat16 g_Qdr   [2ull * MDR * DE_];
__device__ __align__(16) float         g_Kdr   [(size_t)LC_ * DE_];
__device__ __align__(16) __nv_bfloat16 g_Kdrhl [2ull * LC_ * DE_];
__device__ __align__(16) __nv_bfloat16 g_KdrT  [2ull * DE_ * LC_];
__device__ __align__(16) float         g_attdr [(size_t)MDR * LC_];
__device__ __align__(16) __nv_bfloat16 g_attdrhl[2ull * MDR * LC_];

// ---------------------------------------------------------------------------
// mma.sync GEMM: C[m,n] = alpha * sum_k (A_hi+A_lo)[m,k] * (B_hi+B_lo)[n,k]
// 3 register-accumulated passes: (Ah,Bh), (Ah,Bl), (Al,Bh).
// A: [M,K] row-major bf16, B: [N,K] row-major bf16 (both K-major).
// Block tile 128x128, K-stage 32, double-buffered cp.async.
// 8 warps (2m x 4n), warp tile 64x32 = 4x4 m16n8 mma tiles.
// Modes: 0 = f32 store (*alpha,+bias)   1 = f32 accumulate   2 = bf16 hi/lo
// ---------------------------------------------------------------------------
#define STG 10240          // bytes per stage per operand (128 rows * 80B)
#define ROWB 80            // padded row stride bytes (64B data + 16B pad)

__global__ __launch_bounds__(256) void gemm_mma(
    const __nv_bfloat16* __restrict__ A, size_t aLo,
    const __nv_bfloat16* __restrict__ Bm, size_t bLo,
    int K, void* outPtr, size_t outLo, int ldc,
    const float* __restrict__ bias, float alpha, int mode)
{
    __shared__ __align__(16) char smem[4 * STG];   // A0 A1 B0 B1
    const uint32_t sA = smem_u32(smem);
    const uint32_t sB = sA + 2 * STG;

    const int tid = threadIdx.x;
    const int lane = tid & 31;
    const int warp = tid >> 5;
    const int m0 = blockIdx.y * 128;
    const int n0 = blockIdx.x * 128;
    const int wm = (warp & 1) * 64;
    const int wn = (warp >> 1) * 32;

    const __nv_bfloat16* Ap[3] = {A, A, A + aLo};
    const __nv_bfloat16* Bp[3] = {Bm, Bm + bLo, Bm};

    const int Ks = K >> 5;          // k-stages per pass
    const int total = 3 * Ks;

    // global load mapping: chunks c = tid, tid+256; row=c/4, colB=(c%4)*16
    const int lr0 = tid >> 2;
    const int lc0 = (tid & 3) * 16;

    // ldmatrix address bases
    // A frag (m16k16): row = lane&15, colB = (lane>>4)*16
    const int arow = lane & 15;
    const int acol = (lane >> 4) * 16;
    uint32_t aBase[4];
    #pragma unroll
    for (int i = 0; i < 4; i++)
        aBase[i] = sA + (wm + 16 * i + arow) * ROWB + acol;
    // B frag (two n8k16 per x4): row = (lane&7) + ((lane>>4)&1)*8, colB = ((lane>>3)&1)*16
    const int brow = (lane & 7) + ((lane >> 4) & 1) * 8;
    const int bcol = ((lane >> 3) & 1) * 16;
    uint32_t bBase[2];
    #pragma unroll
    for (int j = 0; j < 2; j++)
        bBase[j] = sB + (wn + 16 * j + brow) * ROWB + bcol;

    float acc[4][4][4];
    #pragma unroll
    for (int i = 0; i < 4; i++)
        #pragma unroll
        for (int j = 0; j < 4; j++)
            #pragma unroll
            for (int e = 0; e < 4; e++) acc[i][j][e] = 0.0f;

    // stage loader
    auto load_stage = [&](int s) {
        const int p = s / Ks;
        const int t = s - p * Ks;
        const int buf = s & 1;
        const char* Ag = (const char*)Ap[p];
        const char* Bg = (const char*)Bp[p];
        const size_t kb = (size_t)t * 64;          // 32 elems * 2B
        #pragma unroll
        for (int h = 0; h < 2; h++) {
            const int row = lr0 + h * 64;
            const uint32_t sa = buf * STG + row * ROWB + lc0;
            cpa16(sA + sa, Ag + ((size_t)(m0 + row) * K) * 2 + kb + lc0);
            cpa16(sB + sa, Bg + ((size_t)(n0 + row) * K) * 2 + kb + lc0);
        }
        CP_COMMIT();
    };

    load_stage(0);
    load_stage(1);

    for (int s = 0; s < total; s++) {
        if (s + 1 < total) { CP_WAIT1(); } else { CP_WAIT0(); }
        __syncthreads();

        const int buf = s & 1;
        const uint32_t off = buf * STG;
        #pragma unroll
        for (int kstep = 0; kstep < 2; kstep++) {
            uint32_t aF[4][4], bF[2][4];
            #pragma unroll
            for (int i = 0; i < 4; i++)
                LDSM4(aF[i], aBase[i] + off + kstep * 32);
            #pragma unroll
            for (int j = 0; j < 2; j++)
                LDSM4(bF[j], bBase[j] + off + kstep * 32);
            #pragma unroll
            for (int i = 0; i < 4; i++)
                #pragma unroll
                for (int j = 0; j < 4; j++) {
                    uint32_t bb[2] = {bF[j >> 1][(j & 1) * 2],
                                      bF[j >> 1][(j & 1) * 2 + 1]};
                    MMA16816(acc[i][j], aF[i], bb);
                }
        }
        __syncthreads();
        if (s + 2 < total) load_stage(s + 2);
    }

    // ------------------ epilogue from registers ------------------
    const int mrow = m0 + wm + (lane >> 2);
    const int ncb  = n0 + wn + 2 * (lane & 3);

    #pragma unroll
    for (int j = 0; j < 4; j++) {
        const int n = ncb + 8 * j;
        float badd0 = 0.0f, badd1 = 0.0f;
        if (bias) { badd0 = bias[n]; badd1 = bias[n + 1]; }
        #pragma unroll
        for (int i = 0; i < 4; i++) {
            #pragma unroll
            for (int half = 0; half < 2; half++) {
                const int m = mrow + 16 * i + 8 * half;
                float v0 = acc[i][j][2 * half + 0] * alpha + badd0;
                float v1 = acc[i][j][2 * half + 1] * alpha + badd1;
                if (mode == 2) {
                    __nv_bfloat16* oh = (__nv_bfloat16*)outPtr;
                    const size_t base = (size_t)m * ldc + n;
                    __nv_bfloat16 h0 = __float2bfloat16(v0);
                    __nv_bfloat16 h1 = __float2bfloat16(v1);
                    __nv_bfloat16 l0 = __float2bfloat16(v0 - __bfloat162float(h0));
                    __nv_bfloat16 l1 = __float2bfloat16(v1 - __bfloat162float(h1));
                    __nv_bfloat162 hp; hp.x = h0; hp.y = h1;
                    __nv_bfloat162 lp; lp.x = l0; lp.y = l1;
                    *(__nv_bfloat162*)&oh[base] = hp;
                    *(__nv_bfloat162*)&oh[base + outLo] = lp;
                } else {
                    float* C = (float*)outPtr;
                    const size_t base = (size_t)m * ldc + n;
                    if (mode == 1) {
                        float2 o = *(float2*)&C[base];
                        v0 += o.x; v1 += o.y;
                    }
                    float2 w; w.x = v0; w.y = v1;
                    *(float2*)&C[base] = w;
                }
            }
        }
    }
}

// ---------------------------------------------------------------------------
// fp32 -> bf16 hi/lo split (elementwise, float4 vectorized)
// ---------------------------------------------------------------------------
__global__ __launch_bounds__(256) void split_k(
    const float* __restrict__ in, __nv_bfloat16* __restrict__ oh,
    size_t loOff, int n4)
{
    const int i = blockIdx.x * blockDim.x + threadIdx.x;
    if (i >= n4) return;
    const float4 v = ((const float4*)in)[i];
    const float vv[4] = {v.x, v.y, v.z, v.w};
    __nv_bfloat16 h[4], l[4];
    #pragma unroll
    for (int j = 0; j < 4; j++) {
        h[j] = __float2bfloat16(vv[j]);
        l[j] = __float2bfloat16(vv[j] - __bfloat162float(h[j]));
    }
    *(uint2*)&oh[(size_t)i * 4]         = *(uint2*)h;
    *(uint2*)&oh[loOff + (size_t)i * 4] = *(uint2*)l;
}

// ---------------------------------------------------------------------------
// fp32 [R,C] -> transposed bf16 hi/lo [C,R]
// ---------------------------------------------------------------------------
__global__ __launch_bounds__(256) void tsplit_k(
    const float* __restrict__ in, int R, int C,
    __nv_bfloat16* __restrict__ oh, size_t loOff)
{
    __shared__ float t[32][33];
    const int c0 = blockIdx.x * 32;
    const int rr0 = blockIdx.y * 32;
    const int tx = threadIdx.x;
    const int ty = threadIdx.y;
    #pragma unroll
    for (int i = 0; i < 4; i++)
        t[ty + 8 * i][tx] = in[(size_t)(rr0 + ty + 8 * i) * C + c0 + tx];
    __syncthreads();
    #pragma unroll
    for (int i = 0; i < 4; i++) {
        const float v = t[tx][ty + 8 * i];
        const __nv_bfloat16 hh = __float2bfloat16(v);
        const __nv_bfloat16 ll = __float2bfloat16(v - __bfloat162float(hh));
        const size_t o = (size_t)(c0 + ty + 8 * i) * R + rr0 + tx;
        oh[o] = hh;
        oh[loOff + o] = ll;
    }
}

// ---------------------------------------------------------------------------
// Masked softmax over LC=256 cols -> bf16 hi/lo output
// ---------------------------------------------------------------------------
__global__ __launch_bounds__(256) void softmax_split_k(
    const float* __restrict__ att, const int* __restrict__ mask,
    __nv_bfloat16* __restrict__ oh, size_t loOff)
{
    const int row = blockIdx.x;
    const int c = threadIdx.x;
    const size_t idx = (size_t)row * LC_ + c;

    float v = att[idx];
    if (mask[row] != 0) v = -1e10f;

    __shared__ float red_max[8];
    __shared__ float red_sum[8];
    const int lane = c & 31;
    const int warp = c >> 5;

    float m = v;
    #pragma unroll
    for (int o = 16; o > 0; o >>= 1)
        m = fmaxf(m, __shfl_xor_sync(0xffffffffu, m, o));
    if (lane == 0) red_max[warp] = m;
    __syncthreads();
    float mmax = red_max[0];
    #pragma unroll
    for (int i = 1; i < 8; i++) mmax = fmaxf(mmax, red_max[i]);

    const float e = expf(v - mmax);

    float s = e;
    #pragma unroll
    for (int o = 16; o > 0; o >>= 1)
        s += __shfl_xor_sync(0xffffffffu, s, o);
    if (lane == 0) red_sum[warp] = s;
    __syncthreads();
    float ssum = red_sum[0];
    #pragma unroll
    for (int i = 1; i < 8; i++) ssum += red_sum[i];

    const float p = e / ssum;
    const __nv_bfloat16 hh = __float2bfloat16(p);
    oh[idx] = hh;
    oh[loOff + idx] = __float2bfloat16(p - __bfloat162float(hh));
}

// ---------------------------------------------------------------------------
// Copy drug_f into first half of drug output rows (row stride 2*DE)
// ---------------------------------------------------------------------------
__global__ __launch_bounds__(256) void copy_drug_kernel(
    const float* __restrict__ drug_f, float* __restrict__ out)
{
    const int idx = blockIdx.x * blockDim.x + threadIdx.x;
    if (idx >= MDR * (DE_ / 4)) return;
    const int m = idx / (DE_ / 4);
    const int n4 = idx % (DE_ / 4);
    const float4 v = ((const float4*)drug_f)[(size_t)m * (DE_ / 4) + n4];
    ((float4*)out)[(size_t)m * (2 * DE_ / 4) + n4] = v;
}

// ---------------------------------------------------------------------------
// Launch
// ---------------------------------------------------------------------------
static inline void* sym(const void* s) {
    void* p = 0;
    cudaGetSymbolAddress(&p, s);
    return p;
}

extern "C" void kernel_launch(void* const* d_in, const int* in_sizes, int n_in,
                              void* d_out, int out_size)
{
    const float* pr_f    = (const float*)d_in[0];
    const float* drug_f  = (const float*)d_in[1];
    const float* pr_conf = (const float*)d_in[2];
    const float* dr_conf = (const float*)d_in[3];
    const float* Wq  = (const float*)d_in[4];
    const float* bq  = (const float*)d_in[5];
    const float* Wk  = (const float*)d_in[6];
    const float* bk  = (const float*)d_in[7];
    const float* Wq2 = (const float*)d_in[8];
    const float* bq2 = (const float*)d_in[9];
    const float* Wk2 = (const float*)d_in[10];
    const float* bk2 = (const float*)d_in[11];
    const float* Wpr = (const float*)d_in[12];
    const float* bpr = (const float*)d_in[13];
    const int* pmask = (const int*)d_in[14];
    const int* dmask = (const int*)d_in[15];

    float* out    = (float*)d_out;
    float* pr_out = out;                                  // [16384, 512]
    float* dr_out = out + (size_t)MPR * DE_;              // [4096, 1024]

    __nv_bfloat16* prf    = (__nv_bfloat16*)sym(g_prf);
    __nv_bfloat16* drugf  = (__nv_bfloat16*)sym(g_drugf);
    __nv_bfloat16* prconf = (__nv_bfloat16*)sym(g_prconf);
    __nv_bfloat16* drconf = (__nv_bfloat16*)sym(g_drconf);
    __nv_bfloat16* WqT    = (__nv_bfloat16*)sym(g_WqT);
    __nv_bfloat16* WkT    = (__nv_bfloat16*)sym(g_WkT);
    __nv_bfloat16* Wq2T   = (__nv_bfloat16*)sym(g_Wq2T);
    __nv_bfloat16* Wk2T   = (__nv_bfloat16*)sym(g_Wk2T);
    __nv_bfloat16* WprTt  = (__nv_bfloat16*)sym(g_WprTt);
    __nv_bfloat16* WprTb  = (__nv_bfloat16*)sym(g_WprTb);
    __nv_bfloat16* Qpr    = (__nv_bfloat16*)sym(g_Qpr);
    float*         Kpr    = (float*)sym(g_Kpr);
    __nv_bfloat16* Kprhl  = (__nv_bfloat16*)sym(g_Kprhl);
    __nv_bfloat16* KprT   = (__nv_bfloat16*)sym(g_KprT);
    float*         att    = (float*)sym(g_att);
    __nv_bfloat16* atthl  = (__nv_bfloat16*)sym(g_atthl);
    __nv_bfloat16* Qa     = (__nv_bfloat16*)sym(g_Qa);
    __nv_bfloat16* Qdr    = (__nv_bfloat16*)sym(g_Qdr);
    float*         Kdr    = (float*)sym(g_Kdr);
    __nv_bfloat16* Kdrhl  = (__nv_bfloat16*)sym(g_Kdrhl);
    __nv_bfloat16* KdrT   = (__nv_bfloat16*)sym(g_KdrT);
    float*         attdr  = (float*)sym(g_attdr);
    __nv_bfloat16* attdrhl= (__nv_bfloat16*)sym(g_attdrhl);

    const float pr_alpha = 1.0f / 16.0f;
    const float dr_alpha = 1.0f / sqrtf((float)DE_);

    // ---- input splits (hi/lo) ----
    {
        int n4 = MPR * DP_ / 4;
        split_k<<<(n4 + 255) / 256, 256>>>(pr_f, prf, (size_t)MPR * DP_, n4);
        n4 = MDR * DE_ / 4;
        split_k<<<(n4 + 255) / 256, 256>>>(drug_f, drugf, (size_t)MDR * DE_, n4);
        n4 = LC_ * DP_ / 4;
        split_k<<<(n4 + 255) / 256, 256>>>(pr_conf, prconf, (size_t)LC_ * DP_, n4);
        n4 = LC_ * DE_ / 4;
        split_k<<<(n4 + 255) / 256, 256>>>(dr_conf, drconf, (size_t)LC_ * DE_, n4);
    }
    // ---- weight transposes (hi/lo) ----
    tsplit_k<<<dim3(DP_ / 32, DP_ / 32), dim3(32, 8)>>>(Wq,  DP_, DP_, WqT,  (size_t)DP_ * DP_);
    tsplit_k<<<dim3(DP_ / 32, DP_ / 32), dim3(32, 8)>>>(Wk,  DP_, DP_, WkT,  (size_t)DP_ * DP_);
    tsplit_k<<<dim3(DE_ / 32, DE_ / 32), dim3(32, 8)>>>(Wq2, DE_, DE_, Wq2T, (size_t)DE_ * DE_);
    tsplit_k<<<dim3(DE_ / 32, DE_ / 32), dim3(32, 8)>>>(Wk2, DE_, DE_, Wk2T, (size_t)DE_ * DE_);
    tsplit_k<<<dim3(DE_ / 32, DP_ / 32), dim3(32, 8)>>>(Wpr, DP_, DE_, WprTt, (size_t)DE_ * DP_);
    tsplit_k<<<dim3(DE_ / 32, DP_ / 32), dim3(32, 8)>>>(Wpr + (size_t)DP_ * DE_, DP_, DE_,
                                                        WprTb, (size_t)DE_ * DP_);

    // ---------------- Protein path ----------------
    // Qpr = pr_f @ Wq + bq  -> bf16 hi/lo
    gemm_mma<<<dim3(DP_ / 128, MPR / 128), 256>>>(
        prf, (size_t)MPR * DP_, WqT, (size_t)DP_ * DP_, DP_,
        Qpr, (size_t)MPR * DP_, DP_, bq, 1.0f, 2);
    // Kpr = pr_conf @ Wk + bk  -> f32
    gemm_mma<<<dim3(DP_ / 128, LC_ / 128), 256>>>(
        prconf, (size_t)LC_ * DP_, WkT, (size_t)DP_ * DP_, DP_,
        Kpr, 0, DP_, bk, 1.0f, 0);
    {
        const int n4 = LC_ * DP_ / 4;
        split_k<<<(n4 + 255) / 256, 256>>>(Kpr, Kprhl, (size_t)LC_ * DP_, n4);
    }
    tsplit_k<<<dim3(DP_ / 32, LC_ / 32), dim3(32, 8)>>>(Kpr, LC_, DP_, KprT, (size_t)DP_ * LC_);
    // att = (Qpr @ Kpr^T) / 16  -> f32
    gemm_mma<<<dim3(LC_ / 128, MPR / 128), 256>>>(
        Qpr, (size_t)MPR * DP_, Kprhl, (size_t)LC_ * DP_, DP_,
        att, 0, LC_, (const float*)0, pr_alpha, 0);
    softmax_split_k<<<MPR, 256>>>(att, pmask, atthl, (size_t)MPR * LC_);
    // Qa = att @ Kpr  -> bf16 hi/lo
    gemm_mma<<<dim3(DP_ / 128, MPR / 128), 256>>>(
        atthl, (size_t)MPR * LC_, KprT, (size_t)DP_ * LC_, LC_,
        Qa, (size_t)MPR * DP_, DP_, (const float*)0, 1.0f, 2);
    // pr_out = pr_f @ WprTop + bpr; += Qa @ WprBot
    gemm_mma<<<dim3(DE_ / 128, MPR / 128), 256>>>(
        prf, (size_t)MPR * DP_, WprTt, (size_t)DE_ * DP_, DP_,
        pr_out, 0, DE_, bpr, 1.0f, 0);
    gemm_mma<<<dim3(DE_ / 128, MPR / 128), 256>>>(
        Qa, (size_t)MPR * DP_, WprTb, (size_t)DE_ * DP_, DP_,
        pr_out, 0, DE_, (const float*)0, 1.0f, 1);

    // ---------------- Drug path ----------------
    gemm_mma<<<dim3(DE_ / 128, MDR / 128), 256>>>(
        drugf, (size_t)MDR * DE_, Wq2T, (size_t)DE_ * DE_, DE_,
        Qdr, (size_t)MDR * DE_, DE_, bq2, 1.0f, 2);
    gemm_mma<<<dim3(DE_ / 128, LC_ / 128), 256>>>(
        drconf, (size_t)LC_ * DE_, Wk2T, (size_t)DE_ * DE_, DE_,
        Kdr, 0, DE_, bk2, 1.0f, 0);
    {
        const int n4 = LC_ * DE_ / 4;
        split_k<<<(n4 + 255) / 256, 256>>>(Kdr, Kdrhl, (size_t)LC_ * DE_, n4);
    }
    tsplit_k<<<dim3(DE_ / 32, LC_ / 32), dim3(32, 8)>>>(Kdr, LC_, DE_, KdrT, (size_t)DE_ * LC_);
    gemm_mma<<<dim3(LC_ / 128, MDR / 128), 256>>>(
        Qdr, (size_t)MDR * DE_, Kdrhl, (size_t)LC_ * DE_, DE_,
        attdr, 0, LC_, (const float*)0, dr_alpha, 0);
    softmax_split_k<<<MDR, 256>>>(attdr, dmask, attdrhl, (size_t)MDR * LC_);
    gemm_mma<<<dim3(DE_ / 128, MDR / 128), 256>>>(
        attdrhl, (size_t)MDR * LC_, KdrT, (size_t)DE_ * LC_, LC_,
        dr_out + DE_, 0, 2 * DE_, (const float*)0, 1.0f, 0);

    const int ncopy = MDR * (DE_ / 4);
    copy_drug_kernel<<<(ncopy + 255) / 256, 256>>>(drug_f, dr_out);
}

// round 5
// speedup vs baseline: 4.0256x; 1.7537x over previous
#include <cuda_runtime.h>
#include <cuda_bf16.h>
#include <cstdint>
#include <math.h>

// ---------------------------------------------------------------------------
// Problem constants
// ---------------------------------------------------------------------------
#define B_   16
#define LP_  1024
#define LD_  256
#define DP_  1280
#define DE_  512
#define LC_  256

#define MPR  (B_ * LP_)      // 16384
#define MDR  (B_ * LD_)      // 4096

// ---------------------------------------------------------------------------
// Helpers (sm_80-era path: cp.async + ldmatrix + mma.sync — valid on sm_103 base)
// ---------------------------------------------------------------------------
__device__ __forceinline__ uint32_t smem_u32(const void* p) {
    uint32_t a;
    asm("{ .reg .u64 t; cvta.to.shared.u64 t, %1; cvt.u32.u64 %0, t; }"
        : "=r"(a) : "l"(p));
    return a;
}

__device__ __forceinline__ void cpa16(uint32_t saddr, const void* g) {
    asm volatile("cp.async.cg.shared.global [%0], [%1], 16;"
                 :: "r"(saddr), "l"(g) : "memory");
}
#define CP_COMMIT() asm volatile("cp.async.commit_group;" ::: "memory")
#define CP_WAIT0()  asm volatile("cp.async.wait_group 0;" ::: "memory")
#define CP_WAIT1()  asm volatile("cp.async.wait_group 1;" ::: "memory")

#define LDSM4(r, addr) \
    asm volatile("ldmatrix.sync.aligned.m8n8.x4.shared.b16 {%0,%1,%2,%3}, [%4];" \
        : "=r"((r)[0]), "=r"((r)[1]), "=r"((r)[2]), "=r"((r)[3]) : "r"(addr))

#define MMA16816(d, a, b) \
    asm volatile("mma.sync.aligned.m16n8k16.row.col.f32.bf16.bf16.f32 " \
        "{%0,%1,%2,%3}, {%4,%5,%6,%7}, {%8,%9}, {%0,%1,%2,%3};" \
        : "+f"((d)[0]), "+f"((d)[1]), "+f"((d)[2]), "+f"((d)[3]) \
        : "r"((a)[0]), "r"((a)[1]), "r"((a)[2]), "r"((a)[3]), \
          "r"((b)[0]), "r"((b)[1]))

// ---------------------------------------------------------------------------
// Scratch (bf16 buffers: hi at [0,sz), lo at [sz,2sz)); 16B aligned
// ---------------------------------------------------------------------------
__device__ __align__(16) __nv_bfloat16 g_prf   [2ull * MPR * DP_];
__device__ __align__(16) __nv_bfloat16 g_drugf [2ull * MDR * DE_];
__device__ __align__(16) __nv_bfloat16 g_prconf[2ull * LC_ * DP_];
__device__ __align__(16) __nv_bfloat16 g_drconf[2ull * LC_ * DE_];
__device__ __align__(16) __nv_bfloat16 g_Wqhl  [2ull * DP_ * DP_];
__device__ __align__(16) __nv_bfloat16 g_WkT   [2ull * DP_ * DP_];
__device__ __align__(16) __nv_bfloat16 g_Wq2hl [2ull * DE_ * DE_];
__device__ __align__(16) __nv_bfloat16 g_Wk2T  [2ull * DE_ * DE_];
__device__ __align__(16) __nv_bfloat16 g_WprTt [2ull * DE_ * DP_];
__device__ __align__(16) __nv_bfloat16 g_WprTb [2ull * DE_ * DP_];

__device__ __align__(16) float         g_Kpr   [(size_t)LC_ * DP_];
__device__ __align__(16) __nv_bfloat16 g_Kprhl [2ull * LC_ * DP_];
__device__ __align__(16) float         g_P1T   [(size_t)LC_ * DP_];   // [256,1280]
__device__ __align__(16) __nv_bfloat16 g_P1Thl [2ull * LC_ * DP_];
__device__ __align__(16) float         g_P2T   [(size_t)DE_ * LC_];   // [512,256]
__device__ __align__(16) __nv_bfloat16 g_P2Thl [2ull * DE_ * LC_];
__device__ __align__(16) float         g_att   [(size_t)MPR * LC_];
__device__ __align__(16) __nv_bfloat16 g_atthl [2ull * MPR * LC_];
__device__ __align__(16) float         g_bqrow [LC_];

__device__ __align__(16) float         g_Kdr   [(size_t)LC_ * DE_];
__device__ __align__(16) __nv_bfloat16 g_Kdrhl [2ull * LC_ * DE_];
__device__ __align__(16) __nv_bfloat16 g_KdrT  [2ull * DE_ * LC_];
__device__ __align__(16) float         g_P1dT  [(size_t)LC_ * DE_];   // [256,512]
__device__ __align__(16) __nv_bfloat16 g_P1dThl[2ull * LC_ * DE_];
__device__ __align__(16) float         g_attdr [(size_t)MDR * LC_];
__device__ __align__(16) __nv_bfloat16 g_attdrhl[2ull * MDR * LC_];
__device__ __align__(16) float         g_bq2row[LC_];

// ---------------------------------------------------------------------------
// mma.sync GEMM: C[m,n] = alpha * sum_k (A_hi+A_lo)[m,k] * (B_hi+B_lo)[n,k]
// 3 register-accumulated passes: (Ah,Bh), (Ah,Bl), (Al,Bh).
// A: [M,K] row-major bf16, B: [N,K] row-major bf16 (both K-major).
// Block tile 128x128, K-stage 32, double-buffered cp.async.
// Modes: 0 = f32 store (*alpha,+bias)   1 = f32 accumulate   2 = bf16 hi/lo
// ---------------------------------------------------------------------------
#define STG 10240          // bytes per stage per operand (128 rows * 80B)
#define ROWB 80            // padded row stride bytes (64B data + 16B pad)

__global__ __launch_bounds__(256) void gemm_mma(
    const __nv_bfloat16* __restrict__ A, size_t aLo,
    const __nv_bfloat16* __restrict__ Bm, size_t bLo,
    int K, void* outPtr, size_t outLo, int ldc,
    const float* __restrict__ bias, float alpha, int mode)
{
    __shared__ __align__(16) char smem[4 * STG];   // A0 A1 B0 B1
    const uint32_t sA = smem_u32(smem);
    const uint32_t sB = sA + 2 * STG;

    const int tid = threadIdx.x;
    const int lane = tid & 31;
    const int warp = tid >> 5;
    const int m0 = blockIdx.y * 128;
    const int n0 = blockIdx.x * 128;
    const int wm = (warp & 1) * 64;
    const int wn = (warp >> 1) * 32;

    const __nv_bfloat16* Ap[3] = {A, A, A + aLo};
    const __nv_bfloat16* Bp[3] = {Bm, Bm + bLo, Bm};

    const int Ks = K >> 5;          // k-stages per pass
    const int total = 3 * Ks;

    const int lr0 = tid >> 2;
    const int lc0 = (tid & 3) * 16;

    const int arow = lane & 15;
    const int acol = (lane >> 4) * 16;
    uint32_t aBase[4];
    #pragma unroll
    for (int i = 0; i < 4; i++)
        aBase[i] = sA + (wm + 16 * i + arow) * ROWB + acol;
    const int brow = (lane & 7) + ((lane >> 4) & 1) * 8;
    const int bcol = ((lane >> 3) & 1) * 16;
    uint32_t bBase[2];
    #pragma unroll
    for (int j = 0; j < 2; j++)
        bBase[j] = sB + (wn + 16 * j + brow) * ROWB + bcol;

    float acc[4][4][4];
    #pragma unroll
    for (int i = 0; i < 4; i++)
        #pragma unroll
        for (int j = 0; j < 4; j++)
            #pragma unroll
            for (int e = 0; e < 4; e++) acc[i][j][e] = 0.0f;

    auto load_stage = [&](int s) {
        const int p = s / Ks;
        const int t = s - p * Ks;
        const int buf = s & 1;
        const char* Ag = (const char*)Ap[p];
        const char* Bg = (const char*)Bp[p];
        const size_t kb = (size_t)t * 64;
        #pragma unroll
        for (int h = 0; h < 2; h++) {
            const int row = lr0 + h * 64;
            const uint32_t sa = buf * STG + row * ROWB + lc0;
            cpa16(sA + sa, Ag + ((size_t)(m0 + row) * K) * 2 + kb + lc0);
            cpa16(sB + sa, Bg + ((size_t)(n0 + row) * K) * 2 + kb + lc0);
        }
        CP_COMMIT();
    };

    load_stage(0);
    load_stage(1);

    for (int s = 0; s < total; s++) {
        if (s + 1 < total) { CP_WAIT1(); } else { CP_WAIT0(); }
        __syncthreads();

        const int buf = s & 1;
        const uint32_t off = buf * STG;
        #pragma unroll
        for (int kstep = 0; kstep < 2; kstep++) {
            uint32_t aF[4][4], bF[2][4];
            #pragma unroll
            for (int i = 0; i < 4; i++)
                LDSM4(aF[i], aBase[i] + off + kstep * 32);
            #pragma unroll
            for (int j = 0; j < 2; j++)
                LDSM4(bF[j], bBase[j] + off + kstep * 32);
            #pragma unroll
            for (int i = 0; i < 4; i++)
                #pragma unroll
                for (int j = 0; j < 4; j++) {
                    uint32_t bb[2] = {bF[j >> 1][(j & 1) * 2],
                                      bF[j >> 1][(j & 1) * 2 + 1]};
                    MMA16816(acc[i][j], aF[i], bb);
                }
        }
        __syncthreads();
        if (s + 2 < total) load_stage(s + 2);
    }

    const int mrow = m0 + wm + (lane >> 2);
    const int ncb  = n0 + wn + 2 * (lane & 3);

    #pragma unroll
    for (int j = 0; j < 4; j++) {
        const int n = ncb + 8 * j;
        float badd0 = 0.0f, badd1 = 0.0f;
        if (bias) { badd0 = bias[n]; badd1 = bias[n + 1]; }
        #pragma unroll
        for (int i = 0; i < 4; i++) {
            #pragma unroll
            for (int half = 0; half < 2; half++) {
                const int m = mrow + 16 * i + 8 * half;
                float v0 = acc[i][j][2 * half + 0] * alpha + badd0;
                float v1 = acc[i][j][2 * half + 1] * alpha + badd1;
                if (mode == 2) {
                    __nv_bfloat16* oh = (__nv_bfloat16*)outPtr;
                    const size_t base = (size_t)m * ldc + n;
                    __nv_bfloat16 h0 = __float2bfloat16(v0);
                    __nv_bfloat16 h1 = __float2bfloat16(v1);
                    __nv_bfloat16 l0 = __float2bfloat16(v0 - __bfloat162float(h0));
                    __nv_bfloat16 l1 = __float2bfloat16(v1 - __bfloat162float(h1));
                    __nv_bfloat162 hp; hp.x = h0; hp.y = h1;
                    __nv_bfloat162 lp; lp.x = l0; lp.y = l1;
                    *(__nv_bfloat162*)&oh[base] = hp;
                    *(__nv_bfloat162*)&oh[base + outLo] = lp;
                } else {
                    float* C = (float*)outPtr;
                    const size_t base = (size_t)m * ldc + n;
                    if (mode == 1) {
                        float2 o = *(float2*)&C[base];
                        v0 += o.x; v1 += o.y;
                    }
                    float2 w; w.x = v0; w.y = v1;
                    *(float2*)&C[base] = w;
                }
            }
        }
    }
}

// ---------------------------------------------------------------------------
// fp32 -> bf16 hi/lo split (elementwise, float4 vectorized)
// ---------------------------------------------------------------------------
__global__ __launch_bounds__(256) void split_k(
    const float* __restrict__ in, __nv_bfloat16* __restrict__ oh,
    size_t loOff, int n4)
{
    const int i = blockIdx.x * blockDim.x + threadIdx.x;
    if (i >= n4) return;
    const float4 v = ((const float4*)in)[i];
    const float vv[4] = {v.x, v.y, v.z, v.w};
    __nv_bfloat16 h[4], l[4];
    #pragma unroll
    for (int j = 0; j < 4; j++) {
        h[j] = __float2bfloat16(vv[j]);
        l[j] = __float2bfloat16(vv[j] - __bfloat162float(h[j]));
    }
    *(uint2*)&oh[(size_t)i * 4]         = *(uint2*)h;
    *(uint2*)&oh[loOff + (size_t)i * 4] = *(uint2*)l;
}

// ---------------------------------------------------------------------------
// fp32 [R,C] -> transposed bf16 hi/lo [C,R]
// ---------------------------------------------------------------------------
__global__ __launch_bounds__(256) void tsplit_k(
    const float* __restrict__ in, int R, int C,
    __nv_bfloat16* __restrict__ oh, size_t loOff)
{
    __shared__ float t[32][33];
    const int c0 = blockIdx.x * 32;
    const int rr0 = blockIdx.y * 32;
    const int tx = threadIdx.x;
    const int ty = threadIdx.y;
    #pragma unroll
    for (int i = 0; i < 4; i++)
        t[ty + 8 * i][tx] = in[(size_t)(rr0 + ty + 8 * i) * C + c0 + tx];
    __syncthreads();
    #pragma unroll
    for (int i = 0; i < 4; i++) {
        const float v = t[tx][ty + 8 * i];
        const __nv_bfloat16 hh = __float2bfloat16(v);
        const __nv_bfloat16 ll = __float2bfloat16(v - __bfloat162float(hh));
        const size_t o = (size_t)(c0 + ty + 8 * i) * R + rr0 + tx;
        oh[o] = hh;
        oh[loOff + o] = ll;
    }
}

// ---------------------------------------------------------------------------
// Row-vector contraction: out[c] = alpha * dot(bvec[0:K], Kmat[c, 0:K])
// One block per c (LC_ blocks), 256 threads reduce.
// ---------------------------------------------------------------------------
__global__ __launch_bounds__(256) void bias_row_k(
    const float* __restrict__ bvec, const float* __restrict__ Kmat,
    int K, float alpha, float* __restrict__ outv)
{
    const int c = blockIdx.x;
    const int tid = threadIdx.x;
    float s = 0.0f;
    for (int k = tid; k < K; k += 256)
        s += bvec[k] * Kmat[(size_t)c * K + k];
    __shared__ float red[8];
    const int lane = tid & 31;
    const int warp = tid >> 5;
    #pragma unroll
    for (int o = 16; o > 0; o >>= 1)
        s += __shfl_xor_sync(0xffffffffu, s, o);
    if (lane == 0) red[warp] = s;
    __syncthreads();
    if (tid == 0) {
        float t = 0.0f;
        #pragma unroll
        for (int i = 0; i < 8; i++) t += red[i];
        outv[c] = t * alpha;
    }
}

// ---------------------------------------------------------------------------
// Masked softmax over LC=256 cols -> bf16 hi/lo output
// ---------------------------------------------------------------------------
__global__ __launch_bounds__(256) void softmax_split_k(
    const float* __restrict__ att, const int* __restrict__ mask,
    __nv_bfloat16* __restrict__ oh, size_t loOff)
{
    const int row = blockIdx.x;
    const int c = threadIdx.x;
    const size_t idx = (size_t)row * LC_ + c;

    float v = att[idx];
    if (mask[row] != 0) v = -1e10f;

    __shared__ float red_max[8];
    __shared__ float red_sum[8];
    const int lane = c & 31;
    const int warp = c >> 5;

    float m = v;
    #pragma unroll
    for (int o = 16; o > 0; o >>= 1)
        m = fmaxf(m, __shfl_xor_sync(0xffffffffu, m, o));
    if (lane == 0) red_max[warp] = m;
    __syncthreads();
    float mmax = red_max[0];
    #pragma unroll
    for (int i = 1; i < 8; i++) mmax = fmaxf(mmax, red_max[i]);

    const float e = expf(v - mmax);

    float s = e;
    #pragma unroll
    for (int o = 16; o > 0; o >>= 1)
        s += __shfl_xor_sync(0xffffffffu, s, o);
    if (lane == 0) red_sum[warp] = s;
    __syncthreads();
    float ssum = red_sum[0];
    #pragma unroll
    for (int i = 1; i < 8; i++) ssum += red_sum[i];

    const float p = e / ssum;
    const __nv_bfloat16 hh = __float2bfloat16(p);
    oh[idx] = hh;
    oh[loOff + idx] = __float2bfloat16(p - __bfloat162float(hh));
}

// ---------------------------------------------------------------------------
// Copy drug_f into first half of drug output rows (row stride 2*DE)
// ---------------------------------------------------------------------------
__global__ __launch_bounds__(256) void copy_drug_kernel(
    const float* __restrict__ drug_f, float* __restrict__ out)
{
    const int idx = blockIdx.x * blockDim.x + threadIdx.x;
    if (idx >= MDR * (DE_ / 4)) return;
    const int m = idx / (DE_ / 4);
    const int n4 = idx % (DE_ / 4);
    const float4 v = ((const float4*)drug_f)[(size_t)m * (DE_ / 4) + n4];
    ((float4*)out)[(size_t)m * (2 * DE_ / 4) + n4] = v;
}

// ---------------------------------------------------------------------------
// Launch
// ---------------------------------------------------------------------------
static inline void* sym(const void* s) {
    void* p = 0;
    cudaGetSymbolAddress(&p, s);
    return p;
}

extern "C" void kernel_launch(void* const* d_in, const int* in_sizes, int n_in,
                              void* d_out, int out_size)
{
    const float* pr_f    = (const float*)d_in[0];
    const float* drug_f  = (const float*)d_in[1];
    const float* pr_conf = (const float*)d_in[2];
    const float* dr_conf = (const float*)d_in[3];
    const float* Wq  = (const float*)d_in[4];
    const float* bq  = (const float*)d_in[5];
    const float* Wk  = (const float*)d_in[6];
    const float* bk  = (const float*)d_in[7];
    const float* Wq2 = (const float*)d_in[8];
    const float* bq2 = (const float*)d_in[9];
    const float* Wk2 = (const float*)d_in[10];
    const float* bk2 = (const float*)d_in[11];
    const float* Wpr = (const float*)d_in[12];
    const float* bpr = (const float*)d_in[13];
    const int* pmask = (const int*)d_in[14];
    const int* dmask = (const int*)d_in[15];

    float* out    = (float*)d_out;
    float* pr_out = out;                                  // [16384, 512]
    float* dr_out = out + (size_t)MPR * DE_;              // [4096, 1024]

    __nv_bfloat16* prf    = (__nv_bfloat16*)sym(g_prf);
    __nv_bfloat16* drugf  = (__nv_bfloat16*)sym(g_drugf);
    __nv_bfloat16* prconf = (__nv_bfloat16*)sym(g_prconf);
    __nv_bfloat16* drconf = (__nv_bfloat16*)sym(g_drconf);
    __nv_bfloat16* Wqhl   = (__nv_bfloat16*)sym(g_Wqhl);
    __nv_bfloat16* WkT    = (__nv_bfloat16*)sym(g_WkT);
    __nv_bfloat16* Wq2hl  = (__nv_bfloat16*)sym(g_Wq2hl);
    __nv_bfloat16* Wk2T   = (__nv_bfloat16*)sym(g_Wk2T);
    __nv_bfloat16* WprTt  = (__nv_bfloat16*)sym(g_WprTt);
    __nv_bfloat16* WprTb  = (__nv_bfloat16*)sym(g_WprTb);
    float*         Kpr    = (float*)sym(g_Kpr);
    __nv_bfloat16* Kprhl  = (__nv_bfloat16*)sym(g_Kprhl);
    float*         P1T    = (float*)sym(g_P1T);
    __nv_bfloat16* P1Thl  = (__nv_bfloat16*)sym(g_P1Thl);
    float*         P2T    = (float*)sym(g_P2T);
    __nv_bfloat16* P2Thl  = (__nv_bfloat16*)sym(g_P2Thl);
    float*         att    = (float*)sym(g_att);
    __nv_bfloat16* atthl  = (__nv_bfloat16*)sym(g_atthl);
    float*         bqrow  = (float*)sym(g_bqrow);
    float*         Kdr    = (float*)sym(g_Kdr);
    __nv_bfloat16* Kdrhl  = (__nv_bfloat16*)sym(g_Kdrhl);
    __nv_bfloat16* KdrT   = (__nv_bfloat16*)sym(g_KdrT);
    float*         P1dT   = (float*)sym(g_P1dT);
    __nv_bfloat16* P1dThl = (__nv_bfloat16*)sym(g_P1dThl);
    float*         attdr  = (float*)sym(g_attdr);
    __nv_bfloat16* attdrhl= (__nv_bfloat16*)sym(g_attdrhl);
    float*         bq2row = (float*)sym(g_bq2row);

    const float pr_alpha = 1.0f / 16.0f;
    const float dr_alpha = 1.0f / sqrtf((float)DE_);

    // ---- input/weight splits ----
    {
        int n4 = MPR * DP_ / 4;
        split_k<<<(n4 + 255) / 256, 256>>>(pr_f, prf, (size_t)MPR * DP_, n4);
        n4 = MDR * DE_ / 4;
        split_k<<<(n4 + 255) / 256, 256>>>(drug_f, drugf, (size_t)MDR * DE_, n4);
        n4 = LC_ * DP_ / 4;
        split_k<<<(n4 + 255) / 256, 256>>>(pr_conf, prconf, (size_t)LC_ * DP_, n4);
        n4 = LC_ * DE_ / 4;
        split_k<<<(n4 + 255) / 256, 256>>>(dr_conf, drconf, (size_t)LC_ * DE_, n4);
        n4 = DP_ * DP_ / 4;
        split_k<<<(n4 + 255) / 256, 256>>>(Wq, Wqhl, (size_t)DP_ * DP_, n4);
        n4 = DE_ * DE_ / 4;
        split_k<<<(n4 + 255) / 256, 256>>>(Wq2, Wq2hl, (size_t)DE_ * DE_, n4);
    }
    tsplit_k<<<dim3(DP_ / 32, DP_ / 32), dim3(32, 8)>>>(Wk,  DP_, DP_, WkT,  (size_t)DP_ * DP_);
    tsplit_k<<<dim3(DE_ / 32, DE_ / 32), dim3(32, 8)>>>(Wk2, DE_, DE_, Wk2T, (size_t)DE_ * DE_);
    tsplit_k<<<dim3(DE_ / 32, DP_ / 32), dim3(32, 8)>>>(Wpr, DP_, DE_, WprTt, (size_t)DE_ * DP_);
    tsplit_k<<<dim3(DE_ / 32, DP_ / 32), dim3(32, 8)>>>(Wpr + (size_t)DP_ * DE_, DP_, DE_,
                                                        WprTb, (size_t)DE_ * DP_);

    // ---------------- Protein path ----------------
    // Kpr = pr_conf @ Wk + bk   [256,1280] f32
    gemm_mma<<<dim3(DP_ / 128, LC_ / 128), 256>>>(
        prconf, (size_t)LC_ * DP_, WkT, (size_t)DP_ * DP_, DP_,
        Kpr, 0, DP_, bk, 1.0f, 0);
    {
        const int n4 = LC_ * DP_ / 4;
        split_k<<<(n4 + 255) / 256, 256>>>(Kpr, Kprhl, (size_t)LC_ * DP_, n4);
    }
    // P1T[c,k] = sum_j Kpr[c,j] * Wq[k,j]   [256,1280] f32  (== (Wq @ Kpr^T)^T)
    gemm_mma<<<dim3(DP_ / 128, LC_ / 128), 256>>>(
        Kprhl, (size_t)LC_ * DP_, Wqhl, (size_t)DP_ * DP_, DP_,
        P1T, 0, DP_, (const float*)0, 1.0f, 0);
    {
        const int n4 = LC_ * DP_ / 4;
        split_k<<<(n4 + 255) / 256, 256>>>(P1T, P1Thl, (size_t)LC_ * DP_, n4);
    }
    // bqrow[c] = dot(bq, Kpr[c,:]) / 16
    bias_row_k<<<LC_, 256>>>(bq, Kpr, DP_, pr_alpha, bqrow);
    // att = pr_f @ P1T^T / 16 + bqrow    [16384,256] f32
    gemm_mma<<<dim3(LC_ / 128, MPR / 128), 256>>>(
        prf, (size_t)MPR * DP_, P1Thl, (size_t)LC_ * DP_, DP_,
        att, 0, LC_, bqrow, pr_alpha, 0);
    softmax_split_k<<<MPR, 256>>>(att, pmask, atthl, (size_t)MPR * LC_);
    // P2T[n,c] = sum_j WprBot[j,n] * Kpr[c,j]   [512,256] f32
    gemm_mma<<<dim3(LC_ / 128, DE_ / 128), 256>>>(
        WprTb, (size_t)DE_ * DP_, Kprhl, (size_t)LC_ * DP_, DP_,
        P2T, 0, LC_, (const float*)0, 1.0f, 0);
    {
        const int n4 = DE_ * LC_ / 4;
        split_k<<<(n4 + 255) / 256, 256>>>(P2T, P2Thl, (size_t)DE_ * LC_, n4);
    }
    // pr_out = pr_f @ WprTop + bpr;  += S @ P2T^T
    gemm_mma<<<dim3(DE_ / 128, MPR / 128), 256>>>(
        prf, (size_t)MPR * DP_, WprTt, (size_t)DE_ * DP_, DP_,
        pr_out, 0, DE_, bpr, 1.0f, 0);
    gemm_mma<<<dim3(DE_ / 128, MPR / 128), 256>>>(
        atthl, (size_t)MPR * LC_, P2Thl, (size_t)DE_ * LC_, LC_,
        pr_out, 0, DE_, (const float*)0, 1.0f, 1);

    // ---------------- Drug path ----------------
    // Kdr = dr_conf @ Wk2 + bk2   [256,512] f32
    gemm_mma<<<dim3(DE_ / 128, LC_ / 128), 256>>>(
        drconf, (size_t)LC_ * DE_, Wk2T, (size_t)DE_ * DE_, DE_,
        Kdr, 0, DE_, bk2, 1.0f, 0);
    {
        const int n4 = LC_ * DE_ / 4;
        split_k<<<(n4 + 255) / 256, 256>>>(Kdr, Kdrhl, (size_t)LC_ * DE_, n4);
    }
    tsplit_k<<<dim3(DE_ / 32, LC_ / 32), dim3(32, 8)>>>(Kdr, LC_, DE_, KdrT, (size_t)DE_ * LC_);
    // P1dT[c,k] = sum_j Kdr[c,j] * Wq2[k,j]   [256,512] f32
    gemm_mma<<<dim3(DE_ / 128, LC_ / 128), 256>>>(
        Kdrhl, (size_t)LC_ * DE_, Wq2hl, (size_t)DE_ * DE_, DE_,
        P1dT, 0, DE_, (const float*)0, 1.0f, 0);
    {
        const int n4 = LC_ * DE_ / 4;
        split_k<<<(n4 + 255) / 256, 256>>>(P1dT, P1dThl, (size_t)LC_ * DE_, n4);
    }
    bias_row_k<<<LC_, 256>>>(bq2, Kdr, DE_, dr_alpha, bq2row);
    // att_dr = drug_f @ P1dT^T * dr_alpha + bq2row
    gemm_mma<<<dim3(LC_ / 128, MDR / 128), 256>>>(
        drugf, (size_t)MDR * DE_, P1dThl, (size_t)LC_ * DE_, DE_,
        attdr, 0, LC_, bq2row, dr_alpha, 0);
    softmax_split_k<<<MDR, 256>>>(attdr, dmask, attdrhl, (size_t)MDR * LC_);
    // dr_out[:, 512:1024] = S_dr @ Kdr
    gemm_mma<<<dim3(DE_ / 128, MDR / 128), 256>>>(
        attdrhl, (size_t)MDR * LC_, KdrT, (size_t)DE_ * LC_, LC_,
        dr_out + DE_, 0, 2 * DE_, (const float*)0, 1.0f, 0);

    const int ncopy = MDR * (DE_ / 4);
    copy_drug_kernel<<<(ncopy + 255) / 256, 256>>>(drug_f, dr_out);
}

// round 6
// speedup vs baseline: 5.4271x; 1.3481x over previous
#include <cuda_runtime.h>
#include <cuda_bf16.h>
#include <cstdint>
#include <math.h>

// ---------------------------------------------------------------------------
// Problem constants
// ---------------------------------------------------------------------------
#define B_   16
#define LP_  1024
#define LD_  256
#define DP_  1280
#define DE_  512
#define LC_  256

#define MPR  (B_ * LP_)      // 16384
#define MDR  (B_ * LD_)      // 4096

// ---------------------------------------------------------------------------
// Helpers
// ---------------------------------------------------------------------------
__device__ __forceinline__ uint32_t smem_u32(const void* p) {
    uint32_t a;
    asm("{ .reg .u64 t; cvta.to.shared.u64 t, %1; cvt.u32.u64 %0, t; }"
        : "=r"(a) : "l"(p));
    return a;
}

__device__ __forceinline__ void cpa16(uint32_t saddr, const void* g) {
    asm volatile("cp.async.cg.shared.global [%0], [%1], 16;"
                 :: "r"(saddr), "l"(g) : "memory");
}
#define CP_COMMIT() asm volatile("cp.async.commit_group;" ::: "memory")
#define CP_WAIT0()  asm volatile("cp.async.wait_group 0;" ::: "memory")
#define CP_WAIT1()  asm volatile("cp.async.wait_group 1;" ::: "memory")

#define LDSM4(r, addr) \
    asm volatile("ldmatrix.sync.aligned.m8n8.x4.shared.b16 {%0,%1,%2,%3}, [%4];" \
        : "=r"((r)[0]), "=r"((r)[1]), "=r"((r)[2]), "=r"((r)[3]) : "r"(addr))

#define MMA16816(d, a, b) \
    asm volatile("mma.sync.aligned.m16n8k16.row.col.f32.bf16.bf16.f32 " \
        "{%0,%1,%2,%3}, {%4,%5,%6,%7}, {%8,%9}, {%0,%1,%2,%3};" \
        : "+f"((d)[0]), "+f"((d)[1]), "+f"((d)[2]), "+f"((d)[3]) \
        : "r"((a)[0]), "r"((a)[1]), "r"((a)[2]), "r"((a)[3]), \
          "r"((b)[0]), "r"((b)[1]))

// ---------------------------------------------------------------------------
// Scratch (bf16 buffers: hi at [0,sz), lo at [sz,2sz)); 16B aligned
// ---------------------------------------------------------------------------
__device__ __align__(16) __nv_bfloat16 g_prf   [2ull * MPR * DP_];
__device__ __align__(16) __nv_bfloat16 g_drugf [2ull * MDR * DE_];
__device__ __align__(16) __nv_bfloat16 g_prconf[2ull * LC_ * DP_];
__device__ __align__(16) __nv_bfloat16 g_drconf[2ull * LC_ * DE_];
__device__ __align__(16) __nv_bfloat16 g_Wqhl  [2ull * DP_ * DP_];
__device__ __align__(16) __nv_bfloat16 g_WkT   [2ull * DP_ * DP_];
__device__ __align__(16) __nv_bfloat16 g_Wq2hl [2ull * DE_ * DE_];
__device__ __align__(16) __nv_bfloat16 g_Wk2T  [2ull * DE_ * DE_];
__device__ __align__(16) __nv_bfloat16 g_WprTt [2ull * DE_ * DP_];
__device__ __align__(16) __nv_bfloat16 g_WprTb [2ull * DE_ * DP_];

__device__ __align__(16) float         g_Kpr   [(size_t)LC_ * DP_];
__device__ __align__(16) __nv_bfloat16 g_Kprhl [2ull * LC_ * DP_];
__device__ __align__(16) __nv_bfloat16 g_P1Thl [2ull * LC_ * DP_];
__device__ __align__(16) __nv_bfloat16 g_P2Thl [2ull * DE_ * LC_];
__device__ __align__(16) float         g_att   [(size_t)MPR * LC_];
__device__ __align__(16) __nv_bfloat16 g_atthl [2ull * MPR * LC_];
__device__ __align__(16) float         g_bqrow [LC_];

__device__ __align__(16) float         g_Kdr   [(size_t)LC_ * DE_];
__device__ __align__(16) __nv_bfloat16 g_Kdrhl [2ull * LC_ * DE_];
__device__ __align__(16) __nv_bfloat16 g_KdrT  [2ull * DE_ * LC_];
__device__ __align__(16) __nv_bfloat16 g_P1dThl[2ull * LC_ * DE_];
__device__ __align__(16) float         g_attdr [(size_t)MDR * LC_];
__device__ __align__(16) __nv_bfloat16 g_attdrhl[2ull * MDR * LC_];
__device__ __align__(16) float         g_bq2row[LC_];

// ---------------------------------------------------------------------------
// mma.sync GEMM: C = alpha * (A_hi+A_lo)(B_hi+B_lo)^T (+bias)
// outF: optional f32 output (accumF: read-modify-write). outH: optional bf16
// hi/lo output. Block tile 128x128, K-stage 32, double-buffered cp.async.
// ---------------------------------------------------------------------------
#define STG 10240
#define ROWB 80

__global__ __launch_bounds__(256) void gemm_mma(
    const __nv_bfloat16* __restrict__ A, size_t aLo,
    const __nv_bfloat16* __restrict__ Bm, size_t bLo,
    int K,
    float* __restrict__ outF, int accumF, int ldcF,
    __nv_bfloat16* __restrict__ outH, size_t outLoH, int ldcH,
    const float* __restrict__ bias, float alpha)
{
    __shared__ __align__(16) char smem[4 * STG];
    const uint32_t sA = smem_u32(smem);
    const uint32_t sB = sA + 2 * STG;

    const int tid = threadIdx.x;
    const int lane = tid & 31;
    const int warp = tid >> 5;
    const int m0 = blockIdx.y * 128;
    const int n0 = blockIdx.x * 128;
    const int wm = (warp & 1) * 64;
    const int wn = (warp >> 1) * 32;

    const __nv_bfloat16* Ap[3] = {A, A, A + aLo};
    const __nv_bfloat16* Bp[3] = {Bm, Bm + bLo, Bm};

    const int Ks = K >> 5;
    const int total = 3 * Ks;

    const int lr0 = tid >> 2;
    const int lc0 = (tid & 3) * 16;

    const int arow = lane & 15;
    const int acol = (lane >> 4) * 16;
    uint32_t aBase[4];
    #pragma unroll
    for (int i = 0; i < 4; i++)
        aBase[i] = sA + (wm + 16 * i + arow) * ROWB + acol;
    const int brow = (lane & 7) + ((lane >> 4) & 1) * 8;
    const int bcol = ((lane >> 3) & 1) * 16;
    uint32_t bBase[2];
    #pragma unroll
    for (int j = 0; j < 2; j++)
        bBase[j] = sB + (wn + 16 * j + brow) * ROWB + bcol;

    float acc[4][4][4];
    #pragma unroll
    for (int i = 0; i < 4; i++)
        #pragma unroll
        for (int j = 0; j < 4; j++)
            #pragma unroll
            for (int e = 0; e < 4; e++) acc[i][j][e] = 0.0f;

    auto load_stage = [&](int s) {
        const int p = s / Ks;
        const int t = s - p * Ks;
        const int buf = s & 1;
        const char* Ag = (const char*)Ap[p];
        const char* Bg = (const char*)Bp[p];
        const size_t kb = (size_t)t * 64;
        #pragma unroll
        for (int h = 0; h < 2; h++) {
            const int row = lr0 + h * 64;
            const uint32_t sa = buf * STG + row * ROWB + lc0;
            cpa16(sA + sa, Ag + ((size_t)(m0 + row) * K) * 2 + kb + lc0);
            cpa16(sB + sa, Bg + ((size_t)(n0 + row) * K) * 2 + kb + lc0);
        }
        CP_COMMIT();
    };

    load_stage(0);
    load_stage(1);

    for (int s = 0; s < total; s++) {
        if (s + 1 < total) { CP_WAIT1(); } else { CP_WAIT0(); }
        __syncthreads();

        const int buf = s & 1;
        const uint32_t off = buf * STG;
        #pragma unroll
        for (int kstep = 0; kstep < 2; kstep++) {
            uint32_t aF[4][4], bF[2][4];
            #pragma unroll
            for (int i = 0; i < 4; i++)
                LDSM4(aF[i], aBase[i] + off + kstep * 32);
            #pragma unroll
            for (int j = 0; j < 2; j++)
                LDSM4(bF[j], bBase[j] + off + kstep * 32);
            #pragma unroll
            for (int i = 0; i < 4; i++)
                #pragma unroll
                for (int j = 0; j < 4; j++) {
                    uint32_t bb[2] = {bF[j >> 1][(j & 1) * 2],
                                      bF[j >> 1][(j & 1) * 2 + 1]};
                    MMA16816(acc[i][j], aF[i], bb);
                }
        }
        __syncthreads();
        if (s + 2 < total) load_stage(s + 2);
    }

    const int mrow = m0 + wm + (lane >> 2);
    const int ncb  = n0 + wn + 2 * (lane & 3);

    #pragma unroll
    for (int j = 0; j < 4; j++) {
        const int n = ncb + 8 * j;
        float badd0 = 0.0f, badd1 = 0.0f;
        if (bias) { badd0 = bias[n]; badd1 = bias[n + 1]; }
        #pragma unroll
        for (int i = 0; i < 4; i++) {
            #pragma unroll
            for (int half = 0; half < 2; half++) {
                const int m = mrow + 16 * i + 8 * half;
                float v0 = acc[i][j][2 * half + 0] * alpha + badd0;
                float v1 = acc[i][j][2 * half + 1] * alpha + badd1;
                if (outH) {
                    const size_t base = (size_t)m * ldcH + n;
                    __nv_bfloat16 h0 = __float2bfloat16(v0);
                    __nv_bfloat16 h1 = __float2bfloat16(v1);
                    __nv_bfloat16 l0 = __float2bfloat16(v0 - __bfloat162float(h0));
                    __nv_bfloat16 l1 = __float2bfloat16(v1 - __bfloat162float(h1));
                    __nv_bfloat162 hp; hp.x = h0; hp.y = h1;
                    __nv_bfloat162 lp; lp.x = l0; lp.y = l1;
                    *(__nv_bfloat162*)&outH[base] = hp;
                    *(__nv_bfloat162*)&outH[base + outLoH] = lp;
                }
                if (outF) {
                    const size_t base = (size_t)m * ldcF + n;
                    if (accumF) {
                        float2 o = *(float2*)&outF[base];
                        v0 += o.x; v1 += o.y;
                    }
                    float2 w; w.x = v0; w.y = v1;
                    *(float2*)&outF[base] = w;
                }
            }
        }
    }
}

// ---------------------------------------------------------------------------
// fp32 -> bf16 hi/lo split
// ---------------------------------------------------------------------------
__global__ __launch_bounds__(256) void split_k(
    const float* __restrict__ in, __nv_bfloat16* __restrict__ oh,
    size_t loOff, int n4)
{
    const int i = blockIdx.x * blockDim.x + threadIdx.x;
    if (i >= n4) return;
    const float4 v = ((const float4*)in)[i];
    const float vv[4] = {v.x, v.y, v.z, v.w};
    __nv_bfloat16 h[4], l[4];
    #pragma unroll
    for (int j = 0; j < 4; j++) {
        h[j] = __float2bfloat16(vv[j]);
        l[j] = __float2bfloat16(vv[j] - __bfloat162float(h[j]));
    }
    *(uint2*)&oh[(size_t)i * 4]         = *(uint2*)h;
    *(uint2*)&oh[loOff + (size_t)i * 4] = *(uint2*)l;
}

// ---------------------------------------------------------------------------
// fp32 [R,C] -> transposed bf16 hi/lo [C,R]
// ---------------------------------------------------------------------------
__global__ __launch_bounds__(256) void tsplit_k(
    const float* __restrict__ in, int R, int C,
    __nv_bfloat16* __restrict__ oh, size_t loOff)
{
    __shared__ float t[32][33];
    const int c0 = blockIdx.x * 32;
    const int rr0 = blockIdx.y * 32;
    const int tx = threadIdx.x;
    const int ty = threadIdx.y;
    #pragma unroll
    for (int i = 0; i < 4; i++)
        t[ty + 8 * i][tx] = in[(size_t)(rr0 + ty + 8 * i) * C + c0 + tx];
    __syncthreads();
    #pragma unroll
    for (int i = 0; i < 4; i++) {
        const float v = t[tx][ty + 8 * i];
        const __nv_bfloat16 hh = __float2bfloat16(v);
        const __nv_bfloat16 ll = __float2bfloat16(v - __bfloat162float(hh));
        const size_t o = (size_t)(c0 + ty + 8 * i) * R + rr0 + tx;
        oh[o] = hh;
        oh[loOff + o] = ll;
    }
}

// ---------------------------------------------------------------------------
// out[c] = alpha * dot(bvec, Kmat[c,:])
// ---------------------------------------------------------------------------
__global__ __launch_bounds__(256) void bias_row_k(
    const float* __restrict__ bvec, const float* __restrict__ Kmat,
    int K, float alpha, float* __restrict__ outv)
{
    const int c = blockIdx.x;
    const int tid = threadIdx.x;
    float s = 0.0f;
    for (int k = tid; k < K; k += 256)
        s += bvec[k] * Kmat[(size_t)c * K + k];
    __shared__ float red[8];
    const int lane = tid & 31;
    const int warp = tid >> 5;
    #pragma unroll
    for (int o = 16; o > 0; o >>= 1)
        s += __shfl_xor_sync(0xffffffffu, s, o);
    if (lane == 0) red[warp] = s;
    __syncthreads();
    if (tid == 0) {
        float t = 0.0f;
        #pragma unroll
        for (int i = 0; i < 8; i++) t += red[i];
        outv[c] = t * alpha;
    }
}

// ---------------------------------------------------------------------------
// Masked softmax (LC=256 cols) -> bf16 hi/lo
// ---------------------------------------------------------------------------
__global__ __launch_bounds__(256) void softmax_split_k(
    const float* __restrict__ att, const int* __restrict__ mask,
    __nv_bfloat16* __restrict__ oh, size_t loOff)
{
    const int row = blockIdx.x;
    const int c = threadIdx.x;
    const size_t idx = (size_t)row * LC_ + c;

    float v = att[idx];
    if (mask[row] != 0) v = -1e10f;

    __shared__ float red_max[8];
    __shared__ float red_sum[8];
    const int lane = c & 31;
    const int warp = c >> 5;

    float m = v;
    #pragma unroll
    for (int o = 16; o > 0; o >>= 1)
        m = fmaxf(m, __shfl_xor_sync(0xffffffffu, m, o));
    if (lane == 0) red_max[warp] = m;
    __syncthreads();
    float mmax = red_max[0];
    #pragma unroll
    for (int i = 1; i < 8; i++) mmax = fmaxf(mmax, red_max[i]);

    const float e = expf(v - mmax);

    float s = e;
    #pragma unroll
    for (int o = 16; o > 0; o >>= 1)
        s += __shfl_xor_sync(0xffffffffu, s, o);
    if (lane == 0) red_sum[warp] = s;
    __syncthreads();
    float ssum = red_sum[0];
    #pragma unroll
    for (int i = 1; i < 8; i++) ssum += red_sum[i];

    const float p = e / ssum;
    const __nv_bfloat16 hh = __float2bfloat16(p);
    oh[idx] = hh;
    oh[loOff + idx] = __float2bfloat16(p - __bfloat162float(hh));
}

// ---------------------------------------------------------------------------
// Copy drug_f into first half of drug output rows
// ---------------------------------------------------------------------------
__global__ __launch_bounds__(256) void copy_drug_kernel(
    const float* __restrict__ drug_f, float* __restrict__ out)
{
    const int idx = blockIdx.x * blockDim.x + threadIdx.x;
    if (idx >= MDR * (DE_ / 4)) return;
    const int m = idx / (DE_ / 4);
    const int n4 = idx % (DE_ / 4);
    const float4 v = ((const float4*)drug_f)[(size_t)m * (DE_ / 4) + n4];
    ((float4*)out)[(size_t)m * (2 * DE_ / 4) + n4] = v;
}

// ---------------------------------------------------------------------------
// Launch — forked multi-stream graph
// ---------------------------------------------------------------------------
static inline void* sym(const void* s) {
    void* p = 0;
    cudaGetSymbolAddress(&p, s);
    return p;
}

extern "C" void kernel_launch(void* const* d_in, const int* in_sizes, int n_in,
                              void* d_out, int out_size)
{
    const float* pr_f    = (const float*)d_in[0];
    const float* drug_f  = (const float*)d_in[1];
    const float* pr_conf = (const float*)d_in[2];
    const float* dr_conf = (const float*)d_in[3];
    const float* Wq  = (const float*)d_in[4];
    const float* bq  = (const float*)d_in[5];
    const float* Wk  = (const float*)d_in[6];
    const float* bk  = (const float*)d_in[7];
    const float* Wq2 = (const float*)d_in[8];
    const float* bq2 = (const float*)d_in[9];
    const float* Wk2 = (const float*)d_in[10];
    const float* bk2 = (const float*)d_in[11];
    const float* Wpr = (const float*)d_in[12];
    const float* bpr = (const float*)d_in[13];
    const int* pmask = (const int*)d_in[14];
    const int* dmask = (const int*)d_in[15];

    float* out    = (float*)d_out;
    float* pr_out = out;                                  // [16384, 512]
    float* dr_out = out + (size_t)MPR * DE_;              // [4096, 1024]

    __nv_bfloat16* prf    = (__nv_bfloat16*)sym(g_prf);
    __nv_bfloat16* drugf  = (__nv_bfloat16*)sym(g_drugf);
    __nv_bfloat16* prconf = (__nv_bfloat16*)sym(g_prconf);
    __nv_bfloat16* drconf = (__nv_bfloat16*)sym(g_drconf);
    __nv_bfloat16* Wqhl   = (__nv_bfloat16*)sym(g_Wqhl);
    __nv_bfloat16* WkT    = (__nv_bfloat16*)sym(g_WkT);
    __nv_bfloat16* Wq2hl  = (__nv_bfloat16*)sym(g_Wq2hl);
    __nv_bfloat16* Wk2T   = (__nv_bfloat16*)sym(g_Wk2T);
    __nv_bfloat16* WprTt  = (__nv_bfloat16*)sym(g_WprTt);
    __nv_bfloat16* WprTb  = (__nv_bfloat16*)sym(g_WprTb);
    float*         Kpr    = (float*)sym(g_Kpr);
    __nv_bfloat16* Kprhl  = (__nv_bfloat16*)sym(g_Kprhl);
    __nv_bfloat16* P1Thl  = (__nv_bfloat16*)sym(g_P1Thl);
    __nv_bfloat16* P2Thl  = (__nv_bfloat16*)sym(g_P2Thl);
    float*         att    = (float*)sym(g_att);
    __nv_bfloat16* atthl  = (__nv_bfloat16*)sym(g_atthl);
    float*         bqrow  = (float*)sym(g_bqrow);
    float*         Kdr    = (float*)sym(g_Kdr);
    __nv_bfloat16* Kdrhl  = (__nv_bfloat16*)sym(g_Kdrhl);
    __nv_bfloat16* KdrT   = (__nv_bfloat16*)sym(g_KdrT);
    __nv_bfloat16* P1dThl = (__nv_bfloat16*)sym(g_P1dThl);
    float*         attdr  = (float*)sym(g_attdr);
    __nv_bfloat16* attdrhl= (__nv_bfloat16*)sym(g_attdrhl);
    float*         bq2row = (float*)sym(g_bq2row);

    const float pr_alpha = 1.0f / 16.0f;
    const float dr_alpha = 1.0f / sqrtf((float)DE_);

    cudaStream_t s1, s2;
    cudaStreamCreateWithFlags(&s1, cudaStreamNonBlocking);
    cudaStreamCreateWithFlags(&s2, cudaStreamNonBlocking);
    cudaEvent_t evStart, evA, evQ, evJ1, evJ2;
    cudaEventCreateWithFlags(&evStart, cudaEventDisableTiming);
    cudaEventCreateWithFlags(&evA, cudaEventDisableTiming);
    cudaEventCreateWithFlags(&evQ, cudaEventDisableTiming);
    cudaEventCreateWithFlags(&evJ1, cudaEventDisableTiming);
    cudaEventCreateWithFlags(&evJ2, cudaEventDisableTiming);

    // fork side streams off the captured (default) stream
    cudaEventRecord(evStart, 0);
    cudaStreamWaitEvent(s1, evStart, 0);
    cudaStreamWaitEvent(s2, evStart, 0);

    // ======== stream s1: pr_f split -> prout1 (big independent GEMM) ========
    {
        const int n4 = MPR * DP_ / 4;
        split_k<<<(n4 + 255) / 256, 256, 0, s1>>>(pr_f, prf, (size_t)MPR * DP_, n4);
        cudaEventRecord(evA, s1);     // prf ready
        tsplit_k<<<dim3(DE_ / 32, DP_ / 32), dim3(32, 8), 0, s1>>>(
            Wpr, DP_, DE_, WprTt, (size_t)DE_ * DP_);
        // prout1 = pr_f @ WprTop + bpr
        gemm_mma<<<dim3(DE_ / 128, MPR / 128), 256, 0, s1>>>(
            prf, (size_t)MPR * DP_, WprTt, (size_t)DE_ * DP_, DP_,
            pr_out, 0, DE_, (__nv_bfloat16*)0, 0, 0, bpr, 1.0f);
        cudaEventRecord(evQ, s1);     // pr_out base ready
        copy_drug_kernel<<<(MDR * (DE_ / 4) + 255) / 256, 256, 0, s1>>>(drug_f, dr_out);
        cudaEventRecord(evJ1, s1);
    }

    // ======== stream s2: entire drug path ========
    {
        int n4 = MDR * DE_ / 4;
        split_k<<<(n4 + 255) / 256, 256, 0, s2>>>(drug_f, drugf, (size_t)MDR * DE_, n4);
        n4 = LC_ * DE_ / 4;
        split_k<<<(n4 + 255) / 256, 256, 0, s2>>>(dr_conf, drconf, (size_t)LC_ * DE_, n4);
        n4 = DE_ * DE_ / 4;
        split_k<<<(n4 + 255) / 256, 256, 0, s2>>>(Wq2, Wq2hl, (size_t)DE_ * DE_, n4);
        tsplit_k<<<dim3(DE_ / 32, DE_ / 32), dim3(32, 8), 0, s2>>>(
            Wk2, DE_, DE_, Wk2T, (size_t)DE_ * DE_);
        // Kdr = dr_conf @ Wk2 + bk2 (f32 + hi/lo)
        gemm_mma<<<dim3(DE_ / 128, LC_ / 128), 256, 0, s2>>>(
            drconf, (size_t)LC_ * DE_, Wk2T, (size_t)DE_ * DE_, DE_,
            Kdr, 0, DE_, Kdrhl, (size_t)LC_ * DE_, DE_, bk2, 1.0f);
        tsplit_k<<<dim3(DE_ / 32, LC_ / 32), dim3(32, 8), 0, s2>>>(
            Kdr, LC_, DE_, KdrT, (size_t)DE_ * LC_);
        // P1dT = Kdr @ Wq2^T (hi/lo only)
        gemm_mma<<<dim3(DE_ / 128, LC_ / 128), 256, 0, s2>>>(
            Kdrhl, (size_t)LC_ * DE_, Wq2hl, (size_t)DE_ * DE_, DE_,
            (float*)0, 0, 0, P1dThl, (size_t)LC_ * DE_, DE_, (const float*)0, 1.0f);
        bias_row_k<<<LC_, 256, 0, s2>>>(bq2, Kdr, DE_, dr_alpha, bq2row);
        // att_dr = drug_f @ P1dT^T * dr_alpha + bq2row
        gemm_mma<<<dim3(LC_ / 128, MDR / 128), 256, 0, s2>>>(
            drugf, (size_t)MDR * DE_, P1dThl, (size_t)LC_ * DE_, DE_,
            attdr, 0, LC_, (__nv_bfloat16*)0, 0, 0, bq2row, dr_alpha);
        softmax_split_k<<<MDR, 256, 0, s2>>>(attdr, dmask, attdrhl, (size_t)MDR * LC_);
        // dr_out[:, 512:] = S_dr @ Kdr
        gemm_mma<<<dim3(DE_ / 128, MDR / 128), 256, 0, s2>>>(
            attdrhl, (size_t)MDR * LC_, KdrT, (size_t)DE_ * LC_, LC_,
            dr_out + DE_, 0, 2 * DE_, (__nv_bfloat16*)0, 0, 0, (const float*)0, 1.0f);
        cudaEventRecord(evJ2, s2);
    }

    // ======== stream 0: protein attention chain ========
    {
        int n4 = LC_ * DP_ / 4;
        split_k<<<(n4 + 255) / 256, 256>>>(pr_conf, prconf, (size_t)LC_ * DP_, n4);
        tsplit_k<<<dim3(DP_ / 32, DP_ / 32), dim3(32, 8)>>>(
            Wk, DP_, DP_, WkT, (size_t)DP_ * DP_);
        n4 = DP_ * DP_ / 4;
        split_k<<<(n4 + 255) / 256, 256>>>(Wq, Wqhl, (size_t)DP_ * DP_, n4);
        tsplit_k<<<dim3(DE_ / 32, DP_ / 32), dim3(32, 8)>>>(
            Wpr + (size_t)DP_ * DE_, DP_, DE_, WprTb, (size_t)DE_ * DP_);
        // Kpr = pr_conf @ Wk + bk (f32 + hi/lo)
        gemm_mma<<<dim3(DP_ / 128, LC_ / 128), 256>>>(
            prconf, (size_t)LC_ * DP_, WkT, (size_t)DP_ * DP_, DP_,
            Kpr, 0, DP_, Kprhl, (size_t)LC_ * DP_, DP_, bk, 1.0f);
        // P1T = Kpr @ Wq^T (hi/lo only)
        gemm_mma<<<dim3(DP_ / 128, LC_ / 128), 256>>>(
            Kprhl, (size_t)LC_ * DP_, Wqhl, (size_t)DP_ * DP_, DP_,
            (float*)0, 0, 0, P1Thl, (size_t)LC_ * DP_, DP_, (const float*)0, 1.0f);
        // P2T = WprBot^T-contract with Kpr (hi/lo only)
        gemm_mma<<<dim3(LC_ / 128, DE_ / 128), 256>>>(
            WprTb, (size_t)DE_ * DP_, Kprhl, (size_t)LC_ * DP_, DP_,
            (float*)0, 0, 0, P2Thl, (size_t)DE_ * LC_, LC_, (const float*)0, 1.0f);
        bias_row_k<<<LC_, 256>>>(bq, Kpr, DP_, pr_alpha, bqrow);
        // att = pr_f @ P1T^T / 16 + bqrow  (needs prf from s1)
        cudaStreamWaitEvent(0, evA, 0);
        gemm_mma<<<dim3(LC_ / 128, MPR / 128), 256>>>(
            prf, (size_t)MPR * DP_, P1Thl, (size_t)LC_ * DP_, DP_,
            att, 0, LC_, (__nv_bfloat16*)0, 0, 0, bqrow, pr_alpha);
        softmax_split_k<<<MPR, 256>>>(att, pmask, atthl, (size_t)MPR * LC_);
        // pr_out += S @ P2T^T  (needs prout1 from s1)
        cudaStreamWaitEvent(0, evQ, 0);
        gemm_mma<<<dim3(DE_ / 128, MPR / 128), 256>>>(
            atthl, (size_t)MPR * LC_, P2Thl, (size_t)DE_ * LC_, LC_,
            pr_out, 1, DE_, (__nv_bfloat16*)0, 0, 0, (const float*)0, 1.0f);
    }

    // join side streams back into the captured stream
    cudaStreamWaitEvent(0, evJ1, 0);
    cudaStreamWaitEvent(0, evJ2, 0);

    cudaEventDestroy(evStart);
    cudaEventDestroy(evA);
    cudaEventDestroy(evQ);
    cudaEventDestroy(evJ1);
    cudaEventDestroy(evJ2);
    cudaStreamDestroy(s1);
    cudaStreamDestroy(s2);
}

// round 7
// speedup vs baseline: 6.2957x; 1.1601x over previous
#include <cuda_runtime.h>
#include <cuda_fp16.h>
#include <cstdint>
#include <math.h>

// ---------------------------------------------------------------------------
// Problem constants
// ---------------------------------------------------------------------------
#define B_   16
#define LP_  1024
#define LD_  256
#define DP_  1280
#define DE_  512
#define LC_  256

#define MPR  (B_ * LP_)      // 16384
#define MDR  (B_ * LD_)      // 4096

// ---------------------------------------------------------------------------
// Helpers
// ---------------------------------------------------------------------------
__device__ __forceinline__ uint32_t smem_u32(const void* p) {
    uint32_t a;
    asm("{ .reg .u64 t; cvta.to.shared.u64 t, %1; cvt.u32.u64 %0, t; }"
        : "=r"(a) : "l"(p));
    return a;
}

__device__ __forceinline__ void cpa16(uint32_t saddr, const void* g) {
    asm volatile("cp.async.cg.shared.global [%0], [%1], 16;"
                 :: "r"(saddr), "l"(g) : "memory");
}
#define CP_COMMIT() asm volatile("cp.async.commit_group;" ::: "memory")
#define CP_WAIT0()  asm volatile("cp.async.wait_group 0;" ::: "memory")
#define CP_WAIT1()  asm volatile("cp.async.wait_group 1;" ::: "memory")

#define LDSM4(r, addr) \
    asm volatile("ldmatrix.sync.aligned.m8n8.x4.shared.b16 {%0,%1,%2,%3}, [%4];" \
        : "=r"((r)[0]), "=r"((r)[1]), "=r"((r)[2]), "=r"((r)[3]) : "r"(addr))

#define MMA16816(d, a, b) \
    asm volatile("mma.sync.aligned.m16n8k16.row.col.f32.f16.f16.f32 " \
        "{%0,%1,%2,%3}, {%4,%5,%6,%7}, {%8,%9}, {%0,%1,%2,%3};" \
        : "+f"((d)[0]), "+f"((d)[1]), "+f"((d)[2]), "+f"((d)[3]) \
        : "r"((a)[0]), "r"((a)[1]), "r"((a)[2]), "r"((a)[3]), \
          "r"((b)[0]), "r"((b)[1]))

// ---------------------------------------------------------------------------
// Scratch (fp16; hl buffers: hi at [0,sz), lo at [sz,2sz)); 16B aligned
// ---------------------------------------------------------------------------
__device__ __align__(16) __half g_prf   [(size_t)MPR * DP_];      // hi only
__device__ __align__(16) __half g_drugf [(size_t)MDR * DE_];      // hi only
__device__ __align__(16) __half g_prconf[2ull * LC_ * DP_];
__device__ __align__(16) __half g_drconf[2ull * LC_ * DE_];
__device__ __align__(16) __half g_Wqhl  [2ull * DP_ * DP_];
__device__ __align__(16) __half g_WkT   [2ull * DP_ * DP_];
__device__ __align__(16) __half g_Wq2hl [2ull * DE_ * DE_];
__device__ __align__(16) __half g_Wk2T  [2ull * DE_ * DE_];
__device__ __align__(16) __half g_WprTt [2ull * DE_ * DP_];
__device__ __align__(16) __half g_WprTb [2ull * DE_ * DP_];

__device__ __align__(16) float  g_Kpr   [(size_t)LC_ * DP_];
__device__ __align__(16) __half g_Kprhl [2ull * LC_ * DP_];
__device__ __align__(16) __half g_P1Thl [2ull * LC_ * DP_];
__device__ __align__(16) __half g_P2Thl [2ull * DE_ * LC_];
__device__ __align__(16) float  g_att   [(size_t)MPR * LC_];
__device__ __align__(16) __half g_atthl [(size_t)MPR * LC_];      // hi only
__device__ __align__(16) float  g_bqrow [LC_];

__device__ __align__(16) float  g_Kdr   [(size_t)LC_ * DE_];
__device__ __align__(16) __half g_Kdrhl [2ull * LC_ * DE_];
__device__ __align__(16) __half g_KdrT  [2ull * DE_ * LC_];
__device__ __align__(16) __half g_P1dThl[2ull * LC_ * DE_];
__device__ __align__(16) float  g_attdr [(size_t)MDR * LC_];
__device__ __align__(16) __half g_attdrhl[(size_t)MDR * LC_];     // hi only
__device__ __align__(16) float  g_bq2row[LC_];

// ---------------------------------------------------------------------------
// mma.sync fp16 GEMM: C = alpha * A*B^T (+bias), hi/lo split accumulation.
// nC=3: passes (Ah,Bh),(Ah,Bl),(Al,Bh)   [needs A hi+lo, B hi+lo]
// nC=2: passes (Ah,Bh),(Ah,Bl)           [needs A hi only, B hi+lo]
// A:[M,K], B:[N,K] row-major fp16. Tile 128x128, K-stage 32, double-buffered.
// ---------------------------------------------------------------------------
#define STG 10240
#define ROWB 80

__global__ __launch_bounds__(256) void gemm_mma(
    const __half* __restrict__ A, size_t aLo,
    const __half* __restrict__ Bm, size_t bLo,
    int K, int nC,
    float* __restrict__ outF, int accumF, int ldcF,
    __half* __restrict__ outH, size_t outLoH, int ldcH,
    const float* __restrict__ bias, float alpha)
{
    __shared__ __align__(16) char smem[4 * STG];
    const uint32_t sA = smem_u32(smem);
    const uint32_t sB = sA + 2 * STG;

    const int tid = threadIdx.x;
    const int lane = tid & 31;
    const int warp = tid >> 5;
    const int m0 = blockIdx.y * 128;
    const int n0 = blockIdx.x * 128;
    const int wm = (warp & 1) * 64;
    const int wn = (warp >> 1) * 32;

    const __half* Ap[3] = {A, A, A + aLo};
    const __half* Bp[3] = {Bm, Bm + bLo, Bm};

    const int Ks = K >> 5;
    const int total = nC * Ks;

    const int lr0 = tid >> 2;
    const int lc0 = (tid & 3) * 16;

    const int arow = lane & 15;
    const int acol = (lane >> 4) * 16;
    uint32_t aBase[4];
    #pragma unroll
    for (int i = 0; i < 4; i++)
        aBase[i] = sA + (wm + 16 * i + arow) * ROWB + acol;
    const int brow = (lane & 7) + ((lane >> 4) & 1) * 8;
    const int bcol = ((lane >> 3) & 1) * 16;
    uint32_t bBase[2];
    #pragma unroll
    for (int j = 0; j < 2; j++)
        bBase[j] = sB + (wn + 16 * j + brow) * ROWB + bcol;

    float acc[4][4][4];
    #pragma unroll
    for (int i = 0; i < 4; i++)
        #pragma unroll
        for (int j = 0; j < 4; j++)
            #pragma unroll
            for (int e = 0; e < 4; e++) acc[i][j][e] = 0.0f;

    auto load_stage = [&](int s) {
        const int p = s / Ks;
        const int t = s - p * Ks;
        const int buf = s & 1;
        const char* Ag = (const char*)Ap[p];
        const char* Bg = (const char*)Bp[p];
        const size_t kb = (size_t)t * 64;
        #pragma unroll
        for (int h = 0; h < 2; h++) {
            const int row = lr0 + h * 64;
            const uint32_t sa = buf * STG + row * ROWB + lc0;
            cpa16(sA + sa, Ag + ((size_t)(m0 + row) * K) * 2 + kb + lc0);
            cpa16(sB + sa, Bg + ((size_t)(n0 + row) * K) * 2 + kb + lc0);
        }
        CP_COMMIT();
    };

    load_stage(0);
    load_stage(1);

    for (int s = 0; s < total; s++) {
        if (s + 1 < total) { CP_WAIT1(); } else { CP_WAIT0(); }
        __syncthreads();

        const int buf = s & 1;
        const uint32_t off = buf * STG;
        #pragma unroll
        for (int kstep = 0; kstep < 2; kstep++) {
            uint32_t aF[4][4], bF[2][4];
            #pragma unroll
            for (int i = 0; i < 4; i++)
                LDSM4(aF[i], aBase[i] + off + kstep * 32);
            #pragma unroll
            for (int j = 0; j < 2; j++)
                LDSM4(bF[j], bBase[j] + off + kstep * 32);
            #pragma unroll
            for (int i = 0; i < 4; i++)
                #pragma unroll
                for (int j = 0; j < 4; j++) {
                    uint32_t bb[2] = {bF[j >> 1][(j & 1) * 2],
                                      bF[j >> 1][(j & 1) * 2 + 1]};
                    MMA16816(acc[i][j], aF[i], bb);
                }
        }
        __syncthreads();
        if (s + 2 < total) load_stage(s + 2);
    }

    const int mrow = m0 + wm + (lane >> 2);
    const int ncb  = n0 + wn + 2 * (lane & 3);

    #pragma unroll
    for (int j = 0; j < 4; j++) {
        const int n = ncb + 8 * j;
        float badd0 = 0.0f, badd1 = 0.0f;
        if (bias) { badd0 = bias[n]; badd1 = bias[n + 1]; }
        #pragma unroll
        for (int i = 0; i < 4; i++) {
            #pragma unroll
            for (int half_ = 0; half_ < 2; half_++) {
                const int m = mrow + 16 * i + 8 * half_;
                float v0 = acc[i][j][2 * half_ + 0] * alpha + badd0;
                float v1 = acc[i][j][2 * half_ + 1] * alpha + badd1;
                if (outH) {
                    const size_t base = (size_t)m * ldcH + n;
                    const __half h0 = __float2half(v0);
                    const __half h1 = __float2half(v1);
                    const __half l0 = __float2half(v0 - __half2float(h0));
                    const __half l1 = __float2half(v1 - __half2float(h1));
                    *(__half2*)&outH[base] = __halves2half2(h0, h1);
                    *(__half2*)&outH[base + outLoH] = __halves2half2(l0, l1);
                }
                if (outF) {
                    const size_t base = (size_t)m * ldcF + n;
                    if (accumF) {
                        float2 o = *(float2*)&outF[base];
                        v0 += o.x; v1 += o.y;
                    }
                    float2 w; w.x = v0; w.y = v1;
                    *(float2*)&outF[base] = w;
                }
            }
        }
    }
}

// ---------------------------------------------------------------------------
// fp32 -> fp16 hi/lo split
// ---------------------------------------------------------------------------
__global__ __launch_bounds__(256) void split_k(
    const float* __restrict__ in, __half* __restrict__ oh,
    size_t loOff, int n4)
{
    const int i = blockIdx.x * blockDim.x + threadIdx.x;
    if (i >= n4) return;
    const float4 v = ((const float4*)in)[i];
    const float vv[4] = {v.x, v.y, v.z, v.w};
    __half h[4], l[4];
    #pragma unroll
    for (int j = 0; j < 4; j++) {
        h[j] = __float2half(vv[j]);
        l[j] = __float2half(vv[j] - __half2float(h[j]));
    }
    *(uint2*)&oh[(size_t)i * 4]         = *(uint2*)h;
    *(uint2*)&oh[loOff + (size_t)i * 4] = *(uint2*)l;
}

// fp32 -> fp16 hi only
__global__ __launch_bounds__(256) void split_h(
    const float* __restrict__ in, __half* __restrict__ oh, int n4)
{
    const int i = blockIdx.x * blockDim.x + threadIdx.x;
    if (i >= n4) return;
    const float4 v = ((const float4*)in)[i];
    __half h[4];
    h[0] = __float2half(v.x); h[1] = __float2half(v.y);
    h[2] = __float2half(v.z); h[3] = __float2half(v.w);
    *(uint2*)&oh[(size_t)i * 4] = *(uint2*)h;
}

// ---------------------------------------------------------------------------
// fp32 [R,C] -> transposed fp16 hi/lo [C,R]
// ---------------------------------------------------------------------------
__global__ __launch_bounds__(256) void tsplit_k(
    const float* __restrict__ in, int R, int C,
    __half* __restrict__ oh, size_t loOff)
{
    __shared__ float t[32][33];
    const int c0 = blockIdx.x * 32;
    const int rr0 = blockIdx.y * 32;
    const int tx = threadIdx.x;
    const int ty = threadIdx.y;
    #pragma unroll
    for (int i = 0; i < 4; i++)
        t[ty + 8 * i][tx] = in[(size_t)(rr0 + ty + 8 * i) * C + c0 + tx];
    __syncthreads();
    #pragma unroll
    for (int i = 0; i < 4; i++) {
        const float v = t[tx][ty + 8 * i];
        const __half hh = __float2half(v);
        const __half ll = __float2half(v - __half2float(hh));
        const size_t o = (size_t)(c0 + ty + 8 * i) * R + rr0 + tx;
        oh[o] = hh;
        oh[loOff + o] = ll;
    }
}

// ---------------------------------------------------------------------------
// out[c] = alpha * dot(bvec, Kmat[c,:])
// ---------------------------------------------------------------------------
__global__ __launch_bounds__(256) void bias_row_k(
    const float* __restrict__ bvec, const float* __restrict__ Kmat,
    int K, float alpha, float* __restrict__ outv)
{
    const int c = blockIdx.x;
    const int tid = threadIdx.x;
    float s = 0.0f;
    for (int k = tid; k < K; k += 256)
        s += bvec[k] * Kmat[(size_t)c * K + k];
    __shared__ float red[8];
    const int lane = tid & 31;
    const int warp = tid >> 5;
    #pragma unroll
    for (int o = 16; o > 0; o >>= 1)
        s += __shfl_xor_sync(0xffffffffu, s, o);
    if (lane == 0) red[warp] = s;
    __syncthreads();
    if (tid == 0) {
        float t = 0.0f;
        #pragma unroll
        for (int i = 0; i < 8; i++) t += red[i];
        outv[c] = t * alpha;
    }
}

// ---------------------------------------------------------------------------
// Masked softmax (LC=256 cols) -> fp16 hi
// ---------------------------------------------------------------------------
__global__ __launch_bounds__(256) void softmax_split_k(
    const float* __restrict__ att, const int* __restrict__ mask,
    __half* __restrict__ oh)
{
    const int row = blockIdx.x;
    const int c = threadIdx.x;
    const size_t idx = (size_t)row * LC_ + c;

    float v = att[idx];
    if (mask[row] != 0) v = -1e10f;

    __shared__ float red_max[8];
    __shared__ float red_sum[8];
    const int lane = c & 31;
    const int warp = c >> 5;

    float m = v;
    #pragma unroll
    for (int o = 16; o > 0; o >>= 1)
        m = fmaxf(m, __shfl_xor_sync(0xffffffffu, m, o));
    if (lane == 0) red_max[warp] = m;
    __syncthreads();
    float mmax = red_max[0];
    #pragma unroll
    for (int i = 1; i < 8; i++) mmax = fmaxf(mmax, red_max[i]);

    const float e = expf(v - mmax);

    float s = e;
    #pragma unroll
    for (int o = 16; o > 0; o >>= 1)
        s += __shfl_xor_sync(0xffffffffu, s, o);
    if (lane == 0) red_sum[warp] = s;
    __syncthreads();
    float ssum = red_sum[0];
    #pragma unroll
    for (int i = 1; i < 8; i++) ssum += red_sum[i];

    oh[idx] = __float2half(e / ssum);
}

// ---------------------------------------------------------------------------
// Copy drug_f into first half of drug output rows
// ---------------------------------------------------------------------------
__global__ __launch_bounds__(256) void copy_drug_kernel(
    const float* __restrict__ drug_f, float* __restrict__ out)
{
    const int idx = blockIdx.x * blockDim.x + threadIdx.x;
    if (idx >= MDR * (DE_ / 4)) return;
    const int m = idx / (DE_ / 4);
    const int n4 = idx % (DE_ / 4);
    const float4 v = ((const float4*)drug_f)[(size_t)m * (DE_ / 4) + n4];
    ((float4*)out)[(size_t)m * (2 * DE_ / 4) + n4] = v;
}

// ---------------------------------------------------------------------------
// Launch — forked multi-stream graph
// ---------------------------------------------------------------------------
static inline void* sym(const void* s) {
    void* p = 0;
    cudaGetSymbolAddress(&p, s);
    return p;
}

extern "C" void kernel_launch(void* const* d_in, const int* in_sizes, int n_in,
                              void* d_out, int out_size)
{
    const float* pr_f    = (const float*)d_in[0];
    const float* drug_f  = (const float*)d_in[1];
    const float* pr_conf = (const float*)d_in[2];
    const float* dr_conf = (const float*)d_in[3];
    const float* Wq  = (const float*)d_in[4];
    const float* bq  = (const float*)d_in[5];
    const float* Wk  = (const float*)d_in[6];
    const float* bk  = (const float*)d_in[7];
    const float* Wq2 = (const float*)d_in[8];
    const float* bq2 = (const float*)d_in[9];
    const float* Wk2 = (const float*)d_in[10];
    const float* bk2 = (const float*)d_in[11];
    const float* Wpr = (const float*)d_in[12];
    const float* bpr = (const float*)d_in[13];
    const int* pmask = (const int*)d_in[14];
    const int* dmask = (const int*)d_in[15];

    float* out    = (float*)d_out;
    float* pr_out = out;                                  // [16384, 512]
    float* dr_out = out + (size_t)MPR * DE_;              // [4096, 1024]

    __half* prf    = (__half*)sym(g_prf);
    __half* drugf  = (__half*)sym(g_drugf);
    __half* prconf = (__half*)sym(g_prconf);
    __half* drconf = (__half*)sym(g_drconf);
    __half* Wqhl   = (__half*)sym(g_Wqhl);
    __half* WkT    = (__half*)sym(g_WkT);
    __half* Wq2hl  = (__half*)sym(g_Wq2hl);
    __half* Wk2T   = (__half*)sym(g_Wk2T);
    __half* WprTt  = (__half*)sym(g_WprTt);
    __half* WprTb  = (__half*)sym(g_WprTb);
    float*  Kpr    = (float*)sym(g_Kpr);
    __half* Kprhl  = (__half*)sym(g_Kprhl);
    __half* P1Thl  = (__half*)sym(g_P1Thl);
    __half* P2Thl  = (__half*)sym(g_P2Thl);
    float*  att    = (float*)sym(g_att);
    __half* atthl  = (__half*)sym(g_atthl);
    float*  bqrow  = (float*)sym(g_bqrow);
    float*  Kdr    = (float*)sym(g_Kdr);
    __half* Kdrhl  = (__half*)sym(g_Kdrhl);
    __half* KdrT   = (__half*)sym(g_KdrT);
    __half* P1dThl = (__half*)sym(g_P1dThl);
    float*  attdr  = (float*)sym(g_attdr);
    __half* attdrhl= (__half*)sym(g_attdrhl);
    float*  bq2row = (float*)sym(g_bq2row);

    const float pr_alpha = 1.0f / 16.0f;
    const float dr_alpha = 1.0f / sqrtf((float)DE_);

    cudaStream_t s1, s2;
    cudaStreamCreateWithFlags(&s1, cudaStreamNonBlocking);
    cudaStreamCreateWithFlags(&s2, cudaStreamNonBlocking);
    cudaEvent_t evStart, evA, evQ, evJ1, evJ2;
    cudaEventCreateWithFlags(&evStart, cudaEventDisableTiming);
    cudaEventCreateWithFlags(&evA, cudaEventDisableTiming);
    cudaEventCreateWithFlags(&evQ, cudaEventDisableTiming);
    cudaEventCreateWithFlags(&evJ1, cudaEventDisableTiming);
    cudaEventCreateWithFlags(&evJ2, cudaEventDisableTiming);

    cudaEventRecord(evStart, 0);
    cudaStreamWaitEvent(s1, evStart, 0);
    cudaStreamWaitEvent(s2, evStart, 0);

    // ======== stream s1: pr_f hi-split -> prout1 (big independent GEMM) =====
    {
        const int n4 = MPR * DP_ / 4;
        split_h<<<(n4 + 255) / 256, 256, 0, s1>>>(pr_f, prf, n4);
        cudaEventRecord(evA, s1);     // prf ready
        tsplit_k<<<dim3(DE_ / 32, DP_ / 32), dim3(32, 8), 0, s1>>>(
            Wpr, DP_, DE_, WprTt, (size_t)DE_ * DP_);
        // prout1 = pr_f @ WprTop + bpr   (2-combo)
        gemm_mma<<<dim3(DE_ / 128, MPR / 128), 256, 0, s1>>>(
            prf, 0, WprTt, (size_t)DE_ * DP_, DP_, 2,
            pr_out, 0, DE_, (__half*)0, 0, 0, bpr, 1.0f);
        cudaEventRecord(evQ, s1);     // pr_out base ready
        copy_drug_kernel<<<(MDR * (DE_ / 4) + 255) / 256, 256, 0, s1>>>(drug_f, dr_out);
        cudaEventRecord(evJ1, s1);
    }

    // ======== stream s2: entire drug path ========
    {
        int n4 = MDR * DE_ / 4;
        split_h<<<(n4 + 255) / 256, 256, 0, s2>>>(drug_f, drugf, n4);
        n4 = LC_ * DE_ / 4;
        split_k<<<(n4 + 255) / 256, 256, 0, s2>>>(dr_conf, drconf, (size_t)LC_ * DE_, n4);
        n4 = DE_ * DE_ / 4;
        split_k<<<(n4 + 255) / 256, 256, 0, s2>>>(Wq2, Wq2hl, (size_t)DE_ * DE_, n4);
        tsplit_k<<<dim3(DE_ / 32, DE_ / 32), dim3(32, 8), 0, s2>>>(
            Wk2, DE_, DE_, Wk2T, (size_t)DE_ * DE_);
        // Kdr = dr_conf @ Wk2 + bk2 (3-combo; f32 + hi/lo out)
        gemm_mma<<<dim3(DE_ / 128, LC_ / 128), 256, 0, s2>>>(
            drconf, (size_t)LC_ * DE_, Wk2T, (size_t)DE_ * DE_, DE_, 3,
            Kdr, 0, DE_, Kdrhl, (size_t)LC_ * DE_, DE_, bk2, 1.0f);
        tsplit_k<<<dim3(DE_ / 32, LC_ / 32), dim3(32, 8), 0, s2>>>(
            Kdr, LC_, DE_, KdrT, (size_t)DE_ * LC_);
        // P1dT = Kdr @ Wq2^T (3-combo; hi/lo only)
        gemm_mma<<<dim3(DE_ / 128, LC_ / 128), 256, 0, s2>>>(
            Kdrhl, (size_t)LC_ * DE_, Wq2hl, (size_t)DE_ * DE_, DE_, 3,
            (float*)0, 0, 0, P1dThl, (size_t)LC_ * DE_, DE_, (const float*)0, 1.0f);
        bias_row_k<<<LC_, 256, 0, s2>>>(bq2, Kdr, DE_, dr_alpha, bq2row);
        // att_dr = drug_f @ P1dT^T * dr_alpha + bq2row   (2-combo)
        gemm_mma<<<dim3(LC_ / 128, MDR / 128), 256, 0, s2>>>(
            drugf, 0, P1dThl, (size_t)LC_ * DE_, DE_, 2,
            attdr, 0, LC_, (__half*)0, 0, 0, bq2row, dr_alpha);
        softmax_split_k<<<MDR, 256, 0, s2>>>(attdr, dmask, attdrhl);
        // dr_out[:, 512:] = S_dr @ Kdr   (2-combo)
        gemm_mma<<<dim3(DE_ / 128, MDR / 128), 256, 0, s2>>>(
            attdrhl, 0, KdrT, (size_t)DE_ * LC_, LC_, 2,
            dr_out + DE_, 0, 2 * DE_, (__half*)0, 0, 0, (const float*)0, 1.0f);
        cudaEventRecord(evJ2, s2);
    }

    // ======== stream 0: protein attention chain ========
    {
        int n4 = LC_ * DP_ / 4;
        split_k<<<(n4 + 255) / 256, 256>>>(pr_conf, prconf, (size_t)LC_ * DP_, n4);
        tsplit_k<<<dim3(DP_ / 32, DP_ / 32), dim3(32, 8)>>>(
            Wk, DP_, DP_, WkT, (size_t)DP_ * DP_);
        n4 = DP_ * DP_ / 4;
        split_k<<<(n4 + 255) / 256, 256>>>(Wq, Wqhl, (size_t)DP_ * DP_, n4);
        tsplit_k<<<dim3(DE_ / 32, DP_ / 32), dim3(32, 8)>>>(
            Wpr + (size_t)DP_ * DE_, DP_, DE_, WprTb, (size_t)DE_ * DP_);
        // Kpr = pr_conf @ Wk + bk (3-combo; f32 + hi/lo)
        gemm_mma<<<dim3(DP_ / 128, LC_ / 128), 256>>>(
            prconf, (size_t)LC_ * DP_, WkT, (size_t)DP_ * DP_, DP_, 3,
            Kpr, 0, DP_, Kprhl, (size_t)LC_ * DP_, DP_, bk, 1.0f);
        // P1T = Kpr @ Wq^T (3-combo; hi/lo only)
        gemm_mma<<<dim3(DP_ / 128, LC_ / 128), 256>>>(
            Kprhl, (size_t)LC_ * DP_, Wqhl, (size_t)DP_ * DP_, DP_, 3,
            (float*)0, 0, 0, P1Thl, (size_t)LC_ * DP_, DP_, (const float*)0, 1.0f);
        // P2T = WprBot contracted with Kpr (3-combo; hi/lo only)
        gemm_mma<<<dim3(LC_ / 128, DE_ / 128), 256>>>(
            WprTb, (size_t)DE_ * DP_, Kprhl, (size_t)LC_ * DP_, DP_, 3,
            (float*)0, 0, 0, P2Thl, (size_t)DE_ * LC_, LC_, (const float*)0, 1.0f);
        bias_row_k<<<LC_, 256>>>(bq, Kpr, DP_, pr_alpha, bqrow);
        // att = pr_f @ P1T^T / 16 + bqrow  (2-combo; needs prf from s1)
        cudaStreamWaitEvent(0, evA, 0);
        gemm_mma<<<dim3(LC_ / 128, MPR / 128), 256>>>(
            prf, 0, P1Thl, (size_t)LC_ * DP_, DP_, 2,
            att, 0, LC_, (__half*)0, 0, 0, bqrow, pr_alpha);
        softmax_split_k<<<MPR, 256>>>(att, pmask, atthl);
        // pr_out += S @ P2T^T  (2-combo; needs prout1 from s1)
        cudaStreamWaitEvent(0, evQ, 0);
        gemm_mma<<<dim3(DE_ / 128, MPR / 128), 256>>>(
            atthl, 0, P2Thl, (size_t)DE_ * LC_, LC_, 2,
            pr_out, 1, DE_, (__half*)0, 0, 0, (const float*)0, 1.0f);
    }

    cudaStreamWaitEvent(0, evJ1, 0);
    cudaStreamWaitEvent(0, evJ2, 0);

    cudaEventDestroy(evStart);
    cudaEventDestroy(evA);
    cudaEventDestroy(evQ);
    cudaEventDestroy(evJ1);
    cudaEventDestroy(evJ2);
    cudaStreamDestroy(s1);
    cudaStreamDestroy(s2);
}